// round 4
// baseline (speedup 1.0000x reference)
#include <cuda_runtime.h>
#include <cstdint>
#include <math.h>

#define NTOK 384
#define CDIM 128
#define NROWS (NTOK*NTOK)   /* 147456 */
#define EPSV 1e-5f

// Scratch (no cudaMalloc allowed)
__device__ float g_x    [(size_t)NROWS*CDIM];
__device__ float g_left [(size_t)NROWS*CDIM];
__device__ float g_right[(size_t)NROWS*CDIM];
__device__ float g_gate [(size_t)NROWS*CDIM];
__device__ float g_tri  [(size_t)NROWS*CDIM];

__device__ __forceinline__ float sigmoidf_(float z){ return 1.f/(1.f+expf(-z)); }

__device__ __forceinline__ uint32_t tf32_rna(float f){
  uint32_t r; asm("cvt.rna.tf32.f32 %0, %1;" : "=r"(r) : "f"(f)); return r;
}

// m16n8k8 tf32 mma (sm_80 base ISA — safe on compute_103)
__device__ __forceinline__ void mma_tf32(float& d0, float& d1, float& d2, float& d3,
                                         uint32_t a0, uint32_t a1, uint32_t a2, uint32_t a3,
                                         uint32_t b0, uint32_t b1){
  asm volatile(
    "mma.sync.aligned.m16n8k8.row.col.f32.tf32.tf32.f32 "
    "{%0,%1,%2,%3}, {%4,%5,%6,%7}, {%8,%9}, {%0,%1,%2,%3};"
    : "+f"(d0), "+f"(d1), "+f"(d2), "+f"(d3)
    : "r"(a0), "r"(a1), "r"(a2), "r"(a3), "r"(b0), "r"(b1));
}

// packed fp32x2 FMA (PTX ISA 8.6, base sm_100)
__device__ __forceinline__ void fma2(unsigned long long& d,
                                     unsigned long long a, unsigned long long b){
  asm("fma.rn.f32x2 %0, %1, %2, %0;" : "+l"(d) : "l"(a), "l"(b));
}

// ---------------- Stage 1: LayerNorm over C ----------------
__global__ __launch_bounds__(128) void ln_kernel(const float* __restrict__ act,
                                                 const float* __restrict__ g,
                                                 const float* __restrict__ b){
  int row = blockIdx.x;
  int c   = threadIdx.x;
  float v = act[(size_t)row*CDIM + c];
  float s = v, s2 = v*v;
  #pragma unroll
  for (int off=16; off>0; off>>=1){
    s  += __shfl_xor_sync(0xffffffffu, s,  off);
    s2 += __shfl_xor_sync(0xffffffffu, s2, off);
  }
  __shared__ float sh[8];
  int wid = c>>5, lane = c&31;
  if (lane==0){ sh[wid]=s; sh[4+wid]=s2; }
  __syncthreads();
  float mu = (sh[0]+sh[1]+sh[2]+sh[3]) * (1.f/CDIM);
  float ms = (sh[4]+sh[5]+sh[6]+sh[7]) * (1.f/CDIM);
  float rs = rsqrtf(ms - mu*mu + EPSV);
  g_x[(size_t)row*CDIM + c] = (v-mu)*rs*g[c] + b[c];
}

// ============== Stage 2: projections via tf32 mma.sync ==============
// Row data = 128 words. Strides chosen so stride mod 32 gives conflict-free
// fragment LDS: LDX mod 32 = 4 (A-frag: bank = 4*gid+tig, unique),
// LDW mod 32 = 8 (B-frag: bank = 8*tig+gid, unique).
#define LDX 132
#define LDW 136
#define XS_WORDS (128*LDX)
#define W_WORDS  (128*LDW)
#define PROJ2_SMEM ((XS_WORDS + 2*W_WORDS)*4)
#define PROJ1_SMEM ((XS_WORDS + 1*W_WORDS)*4)

// out[row][n] = mask[row] * (x@W1+bb1) * sigmoid(x@W2+bb2)
__global__ __launch_bounds__(512) void proj2_kernel(const float* __restrict__ mask,
    const float* __restrict__ W1, const float* __restrict__ bb1,
    const float* __restrict__ W2, const float* __restrict__ bb2,
    float* __restrict__ outp){
  extern __shared__ uint32_t sm[];
  uint32_t* xs = sm;
  uint32_t* w1 = sm + XS_WORDS;
  uint32_t* w2 = w1 + W_WORDS;
  int tid  = threadIdx.x;
  int row0 = blockIdx.x * 128;

  // Stage x, W1, W2 (tf32-rounded). 128x128 each, float4-granular.
  #pragma unroll
  for (int it=0; it<8; ++it){
    int slot = tid + it*512;       // 0..4095
    int r  = slot >> 5;            // 0..127  (x-row / W-k)
    int kv = slot & 31;            // float4 index
    float4 v = *reinterpret_cast<const float4*>(&g_x[(size_t)(row0+r)*CDIM + kv*4]);
    uint4 t; t.x=tf32_rna(v.x); t.y=tf32_rna(v.y); t.z=tf32_rna(v.z); t.w=tf32_rna(v.w);
    *reinterpret_cast<uint4*>(&xs[r*LDX + kv*4]) = t;
    v = *reinterpret_cast<const float4*>(&W1[r*CDIM + kv*4]);
    t.x=tf32_rna(v.x); t.y=tf32_rna(v.y); t.z=tf32_rna(v.z); t.w=tf32_rna(v.w);
    *reinterpret_cast<uint4*>(&w1[r*LDW + kv*4]) = t;
    v = *reinterpret_cast<const float4*>(&W2[r*CDIM + kv*4]);
    t.x=tf32_rna(v.x); t.y=tf32_rna(v.y); t.z=tf32_rna(v.z); t.w=tf32_rna(v.w);
    *reinterpret_cast<uint4*>(&w2[r*LDW + kv*4]) = t;
  }
  __syncthreads();

  int lane = tid&31, wid = tid>>5;
  int wm = wid>>2, wn = wid&3;       // 4x4 warp grid; warp tile m32 x n32
  int gid = lane>>2, tig = lane&3;

  float acc1[2][4][4], acc2[2][4][4];
  #pragma unroll
  for (int t=0;t<2;t++)
    #pragma unroll
    for (int u=0;u<4;u++)
      #pragma unroll
      for (int r=0;r<4;r++){ acc1[t][u][r]=0.f; acc2[t][u][r]=0.f; }

  const uint32_t* xa  = xs + (wm*32 + gid)*LDX + tig;
  const uint32_t* wb1 = w1 + tig*LDW + wn*32 + gid;
  const uint32_t* wb2 = w2 + tig*LDW + wn*32 + gid;

  #pragma unroll
  for (int kc=0; kc<16; kc++){
    uint32_t a[2][4];
    #pragma unroll
    for (int t=0;t<2;t++){
      const uint32_t* p = xa + t*16*LDX + kc*8;
      a[t][0] = p[0];
      a[t][1] = p[8*LDX];
      a[t][2] = p[4];
      a[t][3] = p[8*LDX + 4];
    }
    #pragma unroll
    for (int u=0;u<4;u++){
      const uint32_t* q1 = wb1 + kc*8*LDW + u*8;
      const uint32_t* q2 = wb2 + kc*8*LDW + u*8;
      uint32_t b10 = q1[0], b11 = q1[4*LDW];
      uint32_t b20 = q2[0], b21 = q2[4*LDW];
      #pragma unroll
      for (int t=0;t<2;t++){
        mma_tf32(acc1[t][u][0],acc1[t][u][1],acc1[t][u][2],acc1[t][u][3],
                 a[t][0],a[t][1],a[t][2],a[t][3], b10,b11);
        mma_tf32(acc2[t][u][0],acc2[t][u][1],acc2[t][u][2],acc2[t][u][3],
                 a[t][0],a[t][1],a[t][2],a[t][3], b20,b21);
      }
    }
  }

  // Epilogue: bias + sigmoid gate + mask, float2 stores
  #pragma unroll
  for (int t=0;t<2;t++){
    int rowA = row0 + wm*32 + t*16 + gid;
    int rowB = rowA + 8;
    float mvA = mask[rowA], mvB = mask[rowB];
    #pragma unroll
    for (int u=0;u<4;u++){
      int colb = wn*32 + u*8 + 2*tig;
      float bl0 = bb1[colb], bl1 = bb1[colb+1];
      float bg0 = bb2[colb], bg1 = bb2[colb+1];
      float2 oA, oB;
      oA.x = mvA*(acc1[t][u][0]+bl0)*sigmoidf_(acc2[t][u][0]+bg0);
      oA.y = mvA*(acc1[t][u][1]+bl1)*sigmoidf_(acc2[t][u][1]+bg1);
      oB.x = mvB*(acc1[t][u][2]+bl0)*sigmoidf_(acc2[t][u][2]+bg0);
      oB.y = mvB*(acc1[t][u][3]+bl1)*sigmoidf_(acc2[t][u][3]+bg1);
      *reinterpret_cast<float2*>(&outp[(size_t)rowA*CDIM + colb]) = oA;
      *reinterpret_cast<float2*>(&outp[(size_t)rowB*CDIM + colb]) = oB;
    }
  }
}

// gate = sigmoid(x@W1 + bb1)
__global__ __launch_bounds__(512) void proj1_kernel(
    const float* __restrict__ W1, const float* __restrict__ bb1,
    float* __restrict__ outp){
  extern __shared__ uint32_t sm[];
  uint32_t* xs = sm;
  uint32_t* w1 = sm + XS_WORDS;
  int tid  = threadIdx.x;
  int row0 = blockIdx.x * 128;

  #pragma unroll
  for (int it=0; it<8; ++it){
    int slot = tid + it*512;
    int r  = slot >> 5;
    int kv = slot & 31;
    float4 v = *reinterpret_cast<const float4*>(&g_x[(size_t)(row0+r)*CDIM + kv*4]);
    uint4 t; t.x=tf32_rna(v.x); t.y=tf32_rna(v.y); t.z=tf32_rna(v.z); t.w=tf32_rna(v.w);
    *reinterpret_cast<uint4*>(&xs[r*LDX + kv*4]) = t;
    v = *reinterpret_cast<const float4*>(&W1[r*CDIM + kv*4]);
    t.x=tf32_rna(v.x); t.y=tf32_rna(v.y); t.z=tf32_rna(v.z); t.w=tf32_rna(v.w);
    *reinterpret_cast<uint4*>(&w1[r*LDW + kv*4]) = t;
  }
  __syncthreads();

  int lane = tid&31, wid = tid>>5;
  int wm = wid>>2, wn = wid&3;
  int gid = lane>>2, tig = lane&3;

  float acc1[2][4][4];
  #pragma unroll
  for (int t=0;t<2;t++)
    #pragma unroll
    for (int u=0;u<4;u++)
      #pragma unroll
      for (int r=0;r<4;r++) acc1[t][u][r]=0.f;

  const uint32_t* xa  = xs + (wm*32 + gid)*LDX + tig;
  const uint32_t* wb1 = w1 + tig*LDW + wn*32 + gid;

  #pragma unroll
  for (int kc=0; kc<16; kc++){
    uint32_t a[2][4];
    #pragma unroll
    for (int t=0;t<2;t++){
      const uint32_t* p = xa + t*16*LDX + kc*8;
      a[t][0] = p[0];
      a[t][1] = p[8*LDX];
      a[t][2] = p[4];
      a[t][3] = p[8*LDX + 4];
    }
    #pragma unroll
    for (int u=0;u<4;u++){
      const uint32_t* q1 = wb1 + kc*8*LDW + u*8;
      uint32_t b10 = q1[0], b11 = q1[4*LDW];
      #pragma unroll
      for (int t=0;t<2;t++)
        mma_tf32(acc1[t][u][0],acc1[t][u][1],acc1[t][u][2],acc1[t][u][3],
                 a[t][0],a[t][1],a[t][2],a[t][3], b10,b11);
    }
  }

  #pragma unroll
  for (int t=0;t<2;t++){
    int rowA = row0 + wm*32 + t*16 + gid;
    int rowB = rowA + 8;
    #pragma unroll
    for (int u=0;u<4;u++){
      int colb = wn*32 + u*8 + 2*tig;
      float bl0 = bb1[colb], bl1 = bb1[colb+1];
      float2 oA, oB;
      oA.x = sigmoidf_(acc1[t][u][0]+bl0);
      oA.y = sigmoidf_(acc1[t][u][1]+bl1);
      oB.x = sigmoidf_(acc1[t][u][2]+bl0);
      oB.y = sigmoidf_(acc1[t][u][3]+bl1);
      *reinterpret_cast<float2*>(&outp[(size_t)rowA*CDIM + colb]) = oA;
      *reinterpret_cast<float2*>(&outp[(size_t)rowB*CDIM + colb]) = oB;
    }
  }
}

// ============== Stage 3: triangle contraction (f32x2 packed) ==============
// out[i,j,c] = sum_k L[i,k,c]*R[j,k,c].
// 512 threads: 64 channel-pairs x 4 i-splits x 2 j-splits; block tile 16i x 16j x 128c.
typedef unsigned long long ull;
__global__ __launch_bounds__(512) void tri_kernel(){
  int tid = threadIdx.x;
  int tc  = tid & 63;          // channel pair -> c0 = tc*2
  int si  = (tid >> 6) & 3;    // i sub-block (4 rows each)
  int sj  = tid >> 8;          // j sub-block (8 cols each)
  int i0  = blockIdx.x*16 + si*4;
  int j0  = blockIdx.y*16 + sj*8;

  const ull* Lb = reinterpret_cast<const ull*>(g_left)  + (size_t)i0*NTOK*64 + tc;
  const ull* Rb = reinterpret_cast<const ull*>(g_right) + (size_t)j0*NTOK*64 + tc;

  ull acc[32];
  #pragma unroll
  for (int i=0;i<32;i++) acc[i] = 0ull;

  for (int k=0;k<NTOK;k++){
    ull a[4], b[8];
    size_t ko = (size_t)k*64;
    #pragma unroll
    for (int ii=0;ii<4;ii++) a[ii] = Lb[(size_t)ii*NTOK*64 + ko];
    #pragma unroll
    for (int jj=0;jj<8;jj++) b[jj] = Rb[(size_t)jj*NTOK*64 + ko];
    #pragma unroll
    for (int ii=0;ii<4;ii++)
      #pragma unroll
      for (int jj=0;jj<8;jj++)
        fma2(acc[ii*8+jj], a[ii], b[jj]);
  }

  ull* T = reinterpret_cast<ull*>(g_tri);
  #pragma unroll
  for (int ii=0;ii<4;ii++)
    #pragma unroll
    for (int jj=0;jj<8;jj++)
      T[((size_t)(i0+ii)*NTOK + (j0+jj))*64 + tc] = acc[ii*8+jj];
}

// ---------------- fp32 GEMM tile helper (final only) ----------------
__device__ __forceinline__ void gemm_tile(const float* __restrict__ W,
                                          const float* xs_, int xstride,
                                          float* ws_, int tid, int tm, int tr,
                                          float acc[32]){
  #pragma unroll
  for (int i=0;i<32;i++) acc[i]=0.f;
  for (int ch=0; ch<4; ch++){
    __syncthreads();
    #pragma unroll
    for (int q=0;q<32;q++) ws_[q*128+tid] = W[(ch*32+q)*128+tid];
    __syncthreads();
    #pragma unroll
    for (int kk=0;kk<32;kk++){
      float b0 = ws_[kk*128+tm];
      float b1 = ws_[kk*128+tm+32];
      float b2 = ws_[kk*128+tm+64];
      float b3 = ws_[kk*128+tm+96];
      int k = ch*32+kk;
      #pragma unroll
      for (int rr=0;rr<8;rr++){
        float a = xs_[(tr*8+rr)*xstride + k];
        acc[rr*4+0] = fmaf(a,b0,acc[rr*4+0]);
        acc[rr*4+1] = fmaf(a,b1,acc[rr*4+1]);
        acc[rr*4+2] = fmaf(a,b2,acc[rr*4+2]);
        acc[rr*4+3] = fmaf(a,b3,acc[rr*4+3]);
      }
    }
  }
  __syncthreads();
}

// ---------------- Stage 4: LN(tri) @ Wo + bo, * gate ----------------
__global__ __launch_bounds__(128) void final_kernel(const float* __restrict__ cg,
                                                    const float* __restrict__ cb,
                                                    const float* __restrict__ Wo,
                                                    const float* __restrict__ bo,
                                                    float* __restrict__ out){
  __shared__ float ts[32*129];
  __shared__ float ws[32*128];
  __shared__ float mu_s[32], rs_s[32];
  int tid  = threadIdx.x;
  int row0 = blockIdx.x*32;
  #pragma unroll
  for (int r=0;r<32;r++) ts[r*129+tid] = g_tri[(size_t)(row0+r)*CDIM + tid];
  __syncthreads();
  if (tid < 32){
    float s=0.f, s2=0.f;
    #pragma unroll
    for (int k=0;k<128;k++){ float v = ts[tid*129+k]; s+=v; s2+=v*v; }
    float mu = s*(1.f/128.f);
    mu_s[tid] = mu;
    rs_s[tid] = rsqrtf(s2*(1.f/128.f) - mu*mu + EPSV);
  }
  __syncthreads();
  #pragma unroll
  for (int r=0;r<32;r++)
    ts[r*129+tid] = (ts[r*129+tid]-mu_s[r])*rs_s[r]*cg[tid] + cb[tid];

  int tm = tid&31, tr = tid>>5;
  float acc[32];
  gemm_tile(Wo, ts, 129, ws, tid, tm, tr, acc);
  #pragma unroll
  for (int rr=0;rr<8;rr++){
    int row = row0 + tr*8 + rr;
    #pragma unroll
    for (int n=0;n<4;n++){
      int col = tm + 32*n;
      out[(size_t)row*CDIM+col] = (acc[rr*4+n]+bo[col]) * g_gate[(size_t)row*CDIM+col];
    }
  }
}

extern "C" void kernel_launch(void* const* d_in, const int* in_sizes, int n_in,
                              void* d_out, int out_size) {
  const float* act  = (const float*)d_in[0];
  const float* mask = (const float*)d_in[1];
  const float* ln_g = (const float*)d_in[2];
  const float* ln_b = (const float*)d_in[3];
  const float* Wl   = (const float*)d_in[4];
  const float* bl   = (const float*)d_in[5];
  const float* Wr   = (const float*)d_in[6];
  const float* br   = (const float*)d_in[7];
  const float* Wgl  = (const float*)d_in[8];
  const float* bgl  = (const float*)d_in[9];
  const float* Wgr  = (const float*)d_in[10];
  const float* bgr  = (const float*)d_in[11];
  const float* cg   = (const float*)d_in[12];
  const float* cb   = (const float*)d_in[13];
  const float* Wo   = (const float*)d_in[14];
  const float* bo   = (const float*)d_in[15];
  const float* Wg   = (const float*)d_in[16];
  const float* bg   = (const float*)d_in[17];
  float* out = (float*)d_out;

  float *d_left=nullptr, *d_right=nullptr, *d_gate=nullptr;
  cudaGetSymbolAddress((void**)&d_left,  g_left);
  cudaGetSymbolAddress((void**)&d_right, g_right);
  cudaGetSymbolAddress((void**)&d_gate,  g_gate);

  cudaFuncSetAttribute(proj2_kernel, cudaFuncAttributeMaxDynamicSharedMemorySize, PROJ2_SMEM);
  cudaFuncSetAttribute(proj1_kernel, cudaFuncAttributeMaxDynamicSharedMemorySize, PROJ1_SMEM);

  ln_kernel<<<NROWS, 128>>>(act, ln_g, ln_b);
  proj2_kernel<<<NROWS/128, 512, PROJ2_SMEM>>>(mask, Wl, bl, Wgl, bgl, d_left);
  proj2_kernel<<<NROWS/128, 512, PROJ2_SMEM>>>(mask, Wr, br, Wgr, bgr, d_right);
  proj1_kernel<<<NROWS/128, 512, PROJ1_SMEM>>>(Wg, bg, d_gate);
  tri_kernel<<<dim3(NTOK/16, NTOK/16), 512>>>();
  final_kernel<<<NROWS/32, 128>>>(cg, cb, Wo, bo, out);
}

// round 5
// speedup vs baseline: 2.9798x; 2.9798x over previous
#include <cuda_runtime.h>
#include <cuda_bf16.h>
#include <cstdint>
#include <math.h>

#define NTOK 384
#define CDIM 128
#define NROWS (NTOK*NTOK)   /* 147456 */
#define EPSV 1e-5f

// Scratch (no cudaMalloc allowed)
__device__ float g_x   [(size_t)NROWS*CDIM];
__device__ float g_gate[(size_t)NROWS*CDIM];
__device__ float g_tri [(size_t)NROWS*CDIM];           // [c][i*384+j]
__device__ __nv_bfloat16 g_Lhi[(size_t)CDIM*NROWS];    // [c][i*384+k]
__device__ __nv_bfloat16 g_Llo[(size_t)CDIM*NROWS];
__device__ __nv_bfloat16 g_Rhi[(size_t)CDIM*NROWS];    // [c][j*384+k]
__device__ __nv_bfloat16 g_Rlo[(size_t)CDIM*NROWS];

__device__ __forceinline__ float sigmoidf_(float z){ return 1.f/(1.f+expf(-z)); }

__device__ __forceinline__ uint32_t tf32_rna(float f){
  uint32_t r; asm("cvt.rna.tf32.f32 %0, %1;" : "=r"(r) : "f"(f)); return r;
}

// m16n8k8 tf32 mma (sm_80 base ISA)
__device__ __forceinline__ void mma_tf32(float& d0, float& d1, float& d2, float& d3,
                                         uint32_t a0, uint32_t a1, uint32_t a2, uint32_t a3,
                                         uint32_t b0, uint32_t b1){
  asm volatile(
    "mma.sync.aligned.m16n8k8.row.col.f32.tf32.tf32.f32 "
    "{%0,%1,%2,%3}, {%4,%5,%6,%7}, {%8,%9}, {%0,%1,%2,%3};"
    : "+f"(d0), "+f"(d1), "+f"(d2), "+f"(d3)
    : "r"(a0), "r"(a1), "r"(a2), "r"(a3), "r"(b0), "r"(b1));
}

// m16n8k16 bf16 mma (sm_80 base ISA)
__device__ __forceinline__ void mma_bf16(float* d, const uint32_t* a, uint32_t b0, uint32_t b1){
  asm volatile(
    "mma.sync.aligned.m16n8k16.row.col.f32.bf16.bf16.f32 "
    "{%0,%1,%2,%3}, {%4,%5,%6,%7}, {%8,%9}, {%0,%1,%2,%3};"
    : "+f"(d[0]), "+f"(d[1]), "+f"(d[2]), "+f"(d[3])
    : "r"(a[0]), "r"(a[1]), "r"(a[2]), "r"(a[3]), "r"(b0), "r"(b1));
}

// ---------------- Stage 1: LayerNorm over C ----------------
__global__ __launch_bounds__(128) void ln_kernel(const float* __restrict__ act,
                                                 const float* __restrict__ g,
                                                 const float* __restrict__ b){
  int row = blockIdx.x;
  int c   = threadIdx.x;
  float v = act[(size_t)row*CDIM + c];
  float s = v, s2 = v*v;
  #pragma unroll
  for (int off=16; off>0; off>>=1){
    s  += __shfl_xor_sync(0xffffffffu, s,  off);
    s2 += __shfl_xor_sync(0xffffffffu, s2, off);
  }
  __shared__ float sh[8];
  int wid = c>>5, lane = c&31;
  if (lane==0){ sh[wid]=s; sh[4+wid]=s2; }
  __syncthreads();
  float mu = (sh[0]+sh[1]+sh[2]+sh[3]) * (1.f/CDIM);
  float ms = (sh[4]+sh[5]+sh[6]+sh[7]) * (1.f/CDIM);
  float rs = rsqrtf(ms - mu*mu + EPSV);
  g_x[(size_t)row*CDIM + c] = (v-mu)*rs*g[c] + b[c];
}

// ============== Stage 2: projections via tf32 mma.sync ==============
#define LDX 132
#define LDW 136
#define XS_WORDS (128*LDX)
#define W_WORDS  (128*LDW)
#define PROJ2_SMEM ((XS_WORDS + 2*W_WORDS)*4)
#define PROJ1_SMEM ((XS_WORDS + 1*W_WORDS)*4)

// val[row][n] = mask[row]*(x@W1+bb1)*sigmoid(x@W2+bb2), written transposed as bf16 hi/lo
__global__ __launch_bounds__(512) void proj2_kernel(const float* __restrict__ mask,
    const float* __restrict__ W1, const float* __restrict__ bb1,
    const float* __restrict__ W2, const float* __restrict__ bb2,
    __nv_bfloat16* __restrict__ ghi, __nv_bfloat16* __restrict__ glo){
  extern __shared__ uint32_t sm[];
  uint32_t* xs = sm;
  uint32_t* w1 = sm + XS_WORDS;
  uint32_t* w2 = w1 + W_WORDS;
  int tid  = threadIdx.x;
  int row0 = blockIdx.x * 128;

  #pragma unroll
  for (int it=0; it<8; ++it){
    int slot = tid + it*512;
    int r  = slot >> 5;
    int kv = slot & 31;
    float4 v = *reinterpret_cast<const float4*>(&g_x[(size_t)(row0+r)*CDIM + kv*4]);
    uint4 t; t.x=tf32_rna(v.x); t.y=tf32_rna(v.y); t.z=tf32_rna(v.z); t.w=tf32_rna(v.w);
    *reinterpret_cast<uint4*>(&xs[r*LDX + kv*4]) = t;
    v = *reinterpret_cast<const float4*>(&W1[r*CDIM + kv*4]);
    t.x=tf32_rna(v.x); t.y=tf32_rna(v.y); t.z=tf32_rna(v.z); t.w=tf32_rna(v.w);
    *reinterpret_cast<uint4*>(&w1[r*LDW + kv*4]) = t;
    v = *reinterpret_cast<const float4*>(&W2[r*CDIM + kv*4]);
    t.x=tf32_rna(v.x); t.y=tf32_rna(v.y); t.z=tf32_rna(v.z); t.w=tf32_rna(v.w);
    *reinterpret_cast<uint4*>(&w2[r*LDW + kv*4]) = t;
  }
  __syncthreads();

  int lane = tid&31, wid = tid>>5;
  int wm = wid>>2, wn = wid&3;
  int gid = lane>>2, tig = lane&3;

  float acc1[2][4][4], acc2[2][4][4];
  #pragma unroll
  for (int t=0;t<2;t++)
    #pragma unroll
    for (int u=0;u<4;u++)
      #pragma unroll
      for (int r=0;r<4;r++){ acc1[t][u][r]=0.f; acc2[t][u][r]=0.f; }

  const uint32_t* xa  = xs + (wm*32 + gid)*LDX + tig;
  const uint32_t* wb1 = w1 + tig*LDW + wn*32 + gid;
  const uint32_t* wb2 = w2 + tig*LDW + wn*32 + gid;

  #pragma unroll
  for (int kc=0; kc<16; kc++){
    uint32_t a[2][4];
    #pragma unroll
    for (int t=0;t<2;t++){
      const uint32_t* p = xa + t*16*LDX + kc*8;
      a[t][0] = p[0];
      a[t][1] = p[8*LDX];
      a[t][2] = p[4];
      a[t][3] = p[8*LDX + 4];
    }
    #pragma unroll
    for (int u=0;u<4;u++){
      const uint32_t* q1 = wb1 + kc*8*LDW + u*8;
      const uint32_t* q2 = wb2 + kc*8*LDW + u*8;
      uint32_t b10 = q1[0], b11 = q1[4*LDW];
      uint32_t b20 = q2[0], b21 = q2[4*LDW];
      #pragma unroll
      for (int t=0;t<2;t++){
        mma_tf32(acc1[t][u][0],acc1[t][u][1],acc1[t][u][2],acc1[t][u][3],
                 a[t][0],a[t][1],a[t][2],a[t][3], b10,b11);
        mma_tf32(acc2[t][u][0],acc2[t][u][1],acc2[t][u][2],acc2[t][u][3],
                 a[t][0],a[t][1],a[t][2],a[t][3], b20,b21);
      }
    }
  }

  // Epilogue: bias+sigmoid+mask, bf16 split, SMEM transpose -> [c][row] global
  __syncthreads();                 // all warps done reading w1/w2
  __nv_bfloat16* shi = reinterpret_cast<__nv_bfloat16*>(w1);
  __nv_bfloat16* slo = reinterpret_cast<__nv_bfloat16*>(w2);
  #pragma unroll
  for (int t=0;t<2;t++){
    int rA = wm*32 + t*16 + gid;
    int rB = rA + 8;
    float mvA = mask[row0 + rA], mvB = mask[row0 + rB];
    #pragma unroll
    for (int u=0;u<4;u++){
      int colb = wn*32 + u*8 + 2*tig;
      float vals[4];
      vals[0] = mvA*(acc1[t][u][0]+bb1[colb  ])*sigmoidf_(acc2[t][u][0]+bb2[colb  ]);
      vals[1] = mvA*(acc1[t][u][1]+bb1[colb+1])*sigmoidf_(acc2[t][u][1]+bb2[colb+1]);
      vals[2] = mvB*(acc1[t][u][2]+bb1[colb  ])*sigmoidf_(acc2[t][u][2]+bb2[colb  ]);
      vals[3] = mvB*(acc1[t][u][3]+bb1[colb+1])*sigmoidf_(acc2[t][u][3]+bb2[colb+1]);
      int rr[4] = {rA, rA, rB, rB};
      int cc[4] = {colb, colb+1, colb, colb+1};
      #pragma unroll
      for (int q=0;q<4;q++){
        __nv_bfloat16 h = __float2bfloat16(vals[q]);
        shi[cc[q]*128 + rr[q]] = h;
        slo[cc[q]*128 + rr[q]] = __float2bfloat16(vals[q] - __bfloat162float(h));
      }
    }
  }
  __syncthreads();
  {
    int c = tid>>2, q = tid&3;
    const uint4* sh_ = reinterpret_cast<const uint4*>(shi + c*128 + q*32);
    const uint4* sl_ = reinterpret_cast<const uint4*>(slo + c*128 + q*32);
    uint4* dh = reinterpret_cast<uint4*>(ghi + (size_t)c*NROWS + row0 + q*32);
    uint4* dl = reinterpret_cast<uint4*>(glo + (size_t)c*NROWS + row0 + q*32);
    #pragma unroll
    for (int i=0;i<4;i++){ dh[i] = sh_[i]; dl[i] = sl_[i]; }
  }
}

// gate = sigmoid(x@W1 + bb1), [row][c] fp32
__global__ __launch_bounds__(512) void proj1_kernel(
    const float* __restrict__ W1, const float* __restrict__ bb1,
    float* __restrict__ outp){
  extern __shared__ uint32_t sm[];
  uint32_t* xs = sm;
  uint32_t* w1 = sm + XS_WORDS;
  int tid  = threadIdx.x;
  int row0 = blockIdx.x * 128;

  #pragma unroll
  for (int it=0; it<8; ++it){
    int slot = tid + it*512;
    int r  = slot >> 5;
    int kv = slot & 31;
    float4 v = *reinterpret_cast<const float4*>(&g_x[(size_t)(row0+r)*CDIM + kv*4]);
    uint4 t; t.x=tf32_rna(v.x); t.y=tf32_rna(v.y); t.z=tf32_rna(v.z); t.w=tf32_rna(v.w);
    *reinterpret_cast<uint4*>(&xs[r*LDX + kv*4]) = t;
    v = *reinterpret_cast<const float4*>(&W1[r*CDIM + kv*4]);
    t.x=tf32_rna(v.x); t.y=tf32_rna(v.y); t.z=tf32_rna(v.z); t.w=tf32_rna(v.w);
    *reinterpret_cast<uint4*>(&w1[r*LDW + kv*4]) = t;
  }
  __syncthreads();

  int lane = tid&31, wid = tid>>5;
  int wm = wid>>2, wn = wid&3;
  int gid = lane>>2, tig = lane&3;

  float acc1[2][4][4];
  #pragma unroll
  for (int t=0;t<2;t++)
    #pragma unroll
    for (int u=0;u<4;u++)
      #pragma unroll
      for (int r=0;r<4;r++) acc1[t][u][r]=0.f;

  const uint32_t* xa  = xs + (wm*32 + gid)*LDX + tig;
  const uint32_t* wb1 = w1 + tig*LDW + wn*32 + gid;

  #pragma unroll
  for (int kc=0; kc<16; kc++){
    uint32_t a[2][4];
    #pragma unroll
    for (int t=0;t<2;t++){
      const uint32_t* p = xa + t*16*LDX + kc*8;
      a[t][0] = p[0];
      a[t][1] = p[8*LDX];
      a[t][2] = p[4];
      a[t][3] = p[8*LDX + 4];
    }
    #pragma unroll
    for (int u=0;u<4;u++){
      const uint32_t* q1 = wb1 + kc*8*LDW + u*8;
      uint32_t b10 = q1[0], b11 = q1[4*LDW];
      #pragma unroll
      for (int t=0;t<2;t++)
        mma_tf32(acc1[t][u][0],acc1[t][u][1],acc1[t][u][2],acc1[t][u][3],
                 a[t][0],a[t][1],a[t][2],a[t][3], b10,b11);
    }
  }

  #pragma unroll
  for (int t=0;t<2;t++){
    int rowA = row0 + wm*32 + t*16 + gid;
    int rowB = rowA + 8;
    #pragma unroll
    for (int u=0;u<4;u++){
      int colb = wn*32 + u*8 + 2*tig;
      float bl0 = bb1[colb], bl1 = bb1[colb+1];
      float2 oA, oB;
      oA.x = sigmoidf_(acc1[t][u][0]+bl0);
      oA.y = sigmoidf_(acc1[t][u][1]+bl1);
      oB.x = sigmoidf_(acc1[t][u][2]+bl0);
      oB.y = sigmoidf_(acc1[t][u][3]+bl1);
      *reinterpret_cast<float2*>(&outp[(size_t)rowA*CDIM + colb]) = oA;
      *reinterpret_cast<float2*>(&outp[(size_t)rowB*CDIM + colb]) = oB;
    }
  }
}

// ============== Stage 3: per-channel GEMM via bf16-split mma ==============
// out_c[i][j] = sum_k L_c[i][k]*R_c[j][k]; 3-term split: hi*hi + hi*lo + lo*hi.
// Block: 64 i x 128 j tile for one channel c; 256 threads (2x4 warp grid), K chunks of 64.
#define TRI_LDS 72                          /* bf16 row stride: 72%32 group -> conflict-free */
#define TRI_SMEM ((64*TRI_LDS*2 + 128*TRI_LDS*2)*2)
__global__ __launch_bounds__(256) void tri_kernel(){
  extern __shared__ __nv_bfloat16 smb[];
  __nv_bfloat16* Lhi = smb;
  __nv_bfloat16* Llo = smb + 64*TRI_LDS;
  __nv_bfloat16* Rhi = smb + 2*64*TRI_LDS;
  __nv_bfloat16* Rlo = Rhi + 128*TRI_LDS;
  int tid = threadIdx.x;
  int c  = blockIdx.z;
  int i0 = blockIdx.x * 64;
  int j0 = blockIdx.y * 128;
  const __nv_bfloat16* gLh = g_Lhi + (size_t)c*NROWS;
  const __nv_bfloat16* gLl = g_Llo + (size_t)c*NROWS;
  const __nv_bfloat16* gRh = g_Rhi + (size_t)c*NROWS;
  const __nv_bfloat16* gRl = g_Rlo + (size_t)c*NROWS;

  int lane = tid&31, wid = tid>>5;
  int wm = wid>>2, wn = wid&3;           // 2 x 4 warp grid
  int gid = lane>>2, tig = lane&3;

  float acc[2][4][4];
  #pragma unroll
  for (int t=0;t<2;t++)
    #pragma unroll
    for (int u=0;u<4;u++)
      #pragma unroll
      for (int r=0;r<4;r++) acc[t][u][r]=0.f;

  for (int kc=0; kc<NTOK; kc+=64){
    __syncthreads();
    // stage L tiles (64 rows x 64 k)
    #pragma unroll
    for (int it=0; it<2; it++){
      int slot = tid + it*256;
      int r = slot>>3, seg = slot&7;
      size_t go = (size_t)(i0+r)*NTOK + kc + seg*8;
      *reinterpret_cast<uint4*>(&Lhi[r*TRI_LDS + seg*8]) = *reinterpret_cast<const uint4*>(&gLh[go]);
      *reinterpret_cast<uint4*>(&Llo[r*TRI_LDS + seg*8]) = *reinterpret_cast<const uint4*>(&gLl[go]);
    }
    // stage R tiles (128 rows x 64 k)
    #pragma unroll
    for (int it=0; it<4; it++){
      int slot = tid + it*256;
      int r = slot>>3, seg = slot&7;
      size_t go = (size_t)(j0+r)*NTOK + kc + seg*8;
      *reinterpret_cast<uint4*>(&Rhi[r*TRI_LDS + seg*8]) = *reinterpret_cast<const uint4*>(&gRh[go]);
      *reinterpret_cast<uint4*>(&Rlo[r*TRI_LDS + seg*8]) = *reinterpret_cast<const uint4*>(&gRl[go]);
    }
    __syncthreads();

    #pragma unroll
    for (int ks=0; ks<4; ks++){
      int ko = ks*16;
      uint32_t ah[2][4], al[2][4];
      #pragma unroll
      for (int t=0;t<2;t++){
        int row = wm*32 + t*16 + gid;
        int base = row*TRI_LDS + ko + 2*tig;
        ah[t][0] = *reinterpret_cast<const uint32_t*>(&Lhi[base]);
        ah[t][1] = *reinterpret_cast<const uint32_t*>(&Lhi[base + 8*TRI_LDS]);
        ah[t][2] = *reinterpret_cast<const uint32_t*>(&Lhi[base + 8]);
        ah[t][3] = *reinterpret_cast<const uint32_t*>(&Lhi[base + 8*TRI_LDS + 8]);
        al[t][0] = *reinterpret_cast<const uint32_t*>(&Llo[base]);
        al[t][1] = *reinterpret_cast<const uint32_t*>(&Llo[base + 8*TRI_LDS]);
        al[t][2] = *reinterpret_cast<const uint32_t*>(&Llo[base + 8]);
        al[t][3] = *reinterpret_cast<const uint32_t*>(&Llo[base + 8*TRI_LDS + 8]);
      }
      #pragma unroll
      for (int u=0;u<4;u++){
        int jrow = wn*32 + u*8 + gid;
        int bb = jrow*TRI_LDS + ko + 2*tig;
        uint32_t bh0 = *reinterpret_cast<const uint32_t*>(&Rhi[bb]);
        uint32_t bh1 = *reinterpret_cast<const uint32_t*>(&Rhi[bb + 8]);
        uint32_t bl0 = *reinterpret_cast<const uint32_t*>(&Rlo[bb]);
        uint32_t bl1 = *reinterpret_cast<const uint32_t*>(&Rlo[bb + 8]);
        #pragma unroll
        for (int t=0;t<2;t++){
          mma_bf16(acc[t][u], ah[t], bh0, bh1);
          mma_bf16(acc[t][u], ah[t], bl0, bl1);
          mma_bf16(acc[t][u], al[t], bh0, bh1);
        }
      }
    }
  }

  float* To = g_tri + (size_t)c*NROWS;
  #pragma unroll
  for (int t=0;t<2;t++){
    int iA = i0 + wm*32 + t*16 + gid;
    int iB = iA + 8;
    #pragma unroll
    for (int u=0;u<4;u++){
      int j = j0 + wn*32 + u*8 + 2*tig;
      float2 vA = {acc[t][u][0], acc[t][u][1]};
      float2 vB = {acc[t][u][2], acc[t][u][3]};
      *reinterpret_cast<float2*>(&To[(size_t)iA*NTOK + j]) = vA;
      *reinterpret_cast<float2*>(&To[(size_t)iB*NTOK + j]) = vB;
    }
  }
}

// ============== Stage 4: LN(tri) @ Wo + bo, * gate (tf32 mma) ==============
#define LDT 129
#define FINAL_SMEM ((128*LDT + XS_WORDS + W_WORDS)*4)
__global__ __launch_bounds__(512) void final_kernel(const float* __restrict__ cg,
                                                    const float* __restrict__ cb,
                                                    const float* __restrict__ Wo,
                                                    const float* __restrict__ bo,
                                                    float* __restrict__ out){
  extern __shared__ uint32_t sm[];
  float*    T  = reinterpret_cast<float*>(sm);        // [c][ij_local], stride LDT
  uint32_t* xs = sm + 128*LDT;
  uint32_t* w  = xs + XS_WORDS;
  __shared__ float p1[4][128], p2[4][128], mu_s[128], rs_s[128];
  int tid  = threadIdx.x;
  int row0 = blockIdx.x * 128;

  // load tri tile (coalesced per channel) + stage Wo
  #pragma unroll
  for (int it=0; it<8; ++it){
    int slot = tid + it*512;
    int cch = slot >> 5;
    int v4  = slot & 31;
    float4 v = *reinterpret_cast<const float4*>(&g_tri[(size_t)cch*NROWS + row0 + v4*4]);
    T[cch*LDT + v4*4 + 0] = v.x;
    T[cch*LDT + v4*4 + 1] = v.y;
    T[cch*LDT + v4*4 + 2] = v.z;
    T[cch*LDT + v4*4 + 3] = v.w;
    v = *reinterpret_cast<const float4*>(&Wo[cch*CDIM + v4*4]);
    uint4 t; t.x=tf32_rna(v.x); t.y=tf32_rna(v.y); t.z=tf32_rna(v.z); t.w=tf32_rna(v.w);
    *reinterpret_cast<uint4*>(&w[cch*LDW + v4*4]) = t;
  }
  __syncthreads();

  // LN stats per ij row (4-way split over c)
  {
    int ij = tid & 127, pp = tid >> 7;
    float s=0.f, s2=0.f;
    #pragma unroll
    for (int k=0;k<32;k++){
      float v = T[(pp*32+k)*LDT + ij];
      s += v; s2 += v*v;
    }
    p1[pp][ij] = s; p2[pp][ij] = s2;
  }
  __syncthreads();
  if (tid < 128){
    float s  = p1[0][tid]+p1[1][tid]+p1[2][tid]+p1[3][tid];
    float s2 = p2[0][tid]+p2[1][tid]+p2[2][tid]+p2[3][tid];
    float mu = s*(1.f/128.f);
    mu_s[tid] = mu;
    rs_s[tid] = rsqrtf(s2*(1.f/128.f) - mu*mu + EPSV);
  }
  __syncthreads();

  // normalized tf32 A tile: xs[ij][c]
  #pragma unroll
  for (int it=0; it<8; ++it){
    int slot = tid + it*512;
    int r  = slot & 127;
    int cq = slot >> 7;       // 0..31
    float mu = mu_s[r], rs = rs_s[r];
    uint4 t;
    {
      int c0 = cq*4;
      float v0 = (T[(c0+0)*LDT + r]-mu)*rs*cg[c0+0] + cb[c0+0];
      float v1 = (T[(c0+1)*LDT + r]-mu)*rs*cg[c0+1] + cb[c0+1];
      float v2 = (T[(c0+2)*LDT + r]-mu)*rs*cg[c0+2] + cb[c0+2];
      float v3 = (T[(c0+3)*LDT + r]-mu)*rs*cg[c0+3] + cb[c0+3];
      t.x=tf32_rna(v0); t.y=tf32_rna(v1); t.z=tf32_rna(v2); t.w=tf32_rna(v3);
    }
    *reinterpret_cast<uint4*>(&xs[r*LDX + cq*4]) = t;
  }
  __syncthreads();

  int lane = tid&31, wid = tid>>5;
  int wm = wid>>2, wn = wid&3;
  int gid = lane>>2, tig = lane&3;

  float acc[2][4][4];
  #pragma unroll
  for (int t=0;t<2;t++)
    #pragma unroll
    for (int u=0;u<4;u++)
      #pragma unroll
      for (int r=0;r<4;r++) acc[t][u][r]=0.f;

  const uint32_t* xa = xs + (wm*32 + gid)*LDX + tig;
  const uint32_t* wb = w  + tig*LDW + wn*32 + gid;

  #pragma unroll
  for (int kc=0; kc<16; kc++){
    uint32_t a[2][4];
    #pragma unroll
    for (int t=0;t<2;t++){
      const uint32_t* p = xa + t*16*LDX + kc*8;
      a[t][0] = p[0];
      a[t][1] = p[8*LDX];
      a[t][2] = p[4];
      a[t][3] = p[8*LDX + 4];
    }
    #pragma unroll
    for (int u=0;u<4;u++){
      const uint32_t* q1 = wb + kc*8*LDW + u*8;
      uint32_t b10 = q1[0], b11 = q1[4*LDW];
      #pragma unroll
      for (int t=0;t<2;t++)
        mma_tf32(acc[t][u][0],acc[t][u][1],acc[t][u][2],acc[t][u][3],
                 a[t][0],a[t][1],a[t][2],a[t][3], b10,b11);
    }
  }

  #pragma unroll
  for (int t=0;t<2;t++){
    int rowA = row0 + wm*32 + t*16 + gid;
    int rowB = rowA + 8;
    #pragma unroll
    for (int u=0;u<4;u++){
      int colb = wn*32 + u*8 + 2*tig;
      float bo0 = bo[colb], bo1 = bo[colb+1];
      float2 gA = *reinterpret_cast<const float2*>(&g_gate[(size_t)rowA*CDIM + colb]);
      float2 gB = *reinterpret_cast<const float2*>(&g_gate[(size_t)rowB*CDIM + colb]);
      float2 oA, oB;
      oA.x = (acc[t][u][0]+bo0)*gA.x;
      oA.y = (acc[t][u][1]+bo1)*gA.y;
      oB.x = (acc[t][u][2]+bo0)*gB.x;
      oB.y = (acc[t][u][3]+bo1)*gB.y;
      *reinterpret_cast<float2*>(&out[(size_t)rowA*CDIM + colb]) = oA;
      *reinterpret_cast<float2*>(&out[(size_t)rowB*CDIM + colb]) = oB;
    }
  }
}

extern "C" void kernel_launch(void* const* d_in, const int* in_sizes, int n_in,
                              void* d_out, int out_size) {
  const float* act  = (const float*)d_in[0];
  const float* mask = (const float*)d_in[1];
  const float* ln_g = (const float*)d_in[2];
  const float* ln_b = (const float*)d_in[3];
  const float* Wl   = (const float*)d_in[4];
  const float* bl   = (const float*)d_in[5];
  const float* Wr   = (const float*)d_in[6];
  const float* br   = (const float*)d_in[7];
  const float* Wgl  = (const float*)d_in[8];
  const float* bgl  = (const float*)d_in[9];
  const float* Wgr  = (const float*)d_in[10];
  const float* bgr  = (const float*)d_in[11];
  const float* cg   = (const float*)d_in[12];
  const float* cb   = (const float*)d_in[13];
  const float* Wo   = (const float*)d_in[14];
  const float* bo   = (const float*)d_in[15];
  const float* Wg   = (const float*)d_in[16];
  const float* bg   = (const float*)d_in[17];
  float* out = (float*)d_out;

  __nv_bfloat16 *dLh=nullptr, *dLl=nullptr, *dRh=nullptr, *dRl=nullptr;
  float *dGate=nullptr;
  cudaGetSymbolAddress((void**)&dLh, g_Lhi);
  cudaGetSymbolAddress((void**)&dLl, g_Llo);
  cudaGetSymbolAddress((void**)&dRh, g_Rhi);
  cudaGetSymbolAddress((void**)&dRl, g_Rlo);
  cudaGetSymbolAddress((void**)&dGate, g_gate);

  cudaFuncSetAttribute(proj2_kernel, cudaFuncAttributeMaxDynamicSharedMemorySize, PROJ2_SMEM);
  cudaFuncSetAttribute(proj1_kernel, cudaFuncAttributeMaxDynamicSharedMemorySize, PROJ1_SMEM);
  cudaFuncSetAttribute(tri_kernel,   cudaFuncAttributeMaxDynamicSharedMemorySize, TRI_SMEM);
  cudaFuncSetAttribute(final_kernel, cudaFuncAttributeMaxDynamicSharedMemorySize, FINAL_SMEM);

  ln_kernel<<<NROWS, 128>>>(act, ln_g, ln_b);
  proj2_kernel<<<NROWS/128, 512, PROJ2_SMEM>>>(mask, Wl, bl, Wgl, bgl, dLh, dLl);
  proj2_kernel<<<NROWS/128, 512, PROJ2_SMEM>>>(mask, Wr, br, Wgr, bgr, dRh, dRl);
  proj1_kernel<<<NROWS/128, 512, PROJ1_SMEM>>>(Wg, bg, dGate);
  tri_kernel<<<dim3(NTOK/64, NTOK/128, CDIM), 256, TRI_SMEM>>>();
  final_kernel<<<NROWS/128, 512, FINAL_SMEM>>>(cg, cb, Wo, bo, out);
}

// round 6
// speedup vs baseline: 3.5605x; 1.1949x over previous
#include <cuda_runtime.h>
#include <cuda_bf16.h>
#include <cstdint>
#include <math.h>

#define NTOK 384
#define CDIM 128
#define NROWS (NTOK*NTOK)   /* 147456 */
#define EPSV 1e-5f

// Scratch (no cudaMalloc allowed)
__device__ float g_gate[(size_t)NROWS*CDIM];
__device__ float g_tri [(size_t)NROWS*CDIM];           // [c][i*384+j]
__device__ __nv_bfloat16 g_Lhi[(size_t)CDIM*NROWS];    // [c][i*384+k]
__device__ __nv_bfloat16 g_Llo[(size_t)CDIM*NROWS];
__device__ __nv_bfloat16 g_Rhi[(size_t)CDIM*NROWS];    // [c][j*384+k]
__device__ __nv_bfloat16 g_Rlo[(size_t)CDIM*NROWS];

__device__ __forceinline__ float sigmoidf_(float z){ return 1.f/(1.f+expf(-z)); }

__device__ __forceinline__ uint32_t tf32_rna(float f){
  uint32_t r; asm("cvt.rna.tf32.f32 %0, %1;" : "=r"(r) : "f"(f)); return r;
}

// m16n8k8 tf32 mma (sm_80 base ISA)
__device__ __forceinline__ void mma_tf32(float& d0, float& d1, float& d2, float& d3,
                                         uint32_t a0, uint32_t a1, uint32_t a2, uint32_t a3,
                                         uint32_t b0, uint32_t b1){
  asm volatile(
    "mma.sync.aligned.m16n8k8.row.col.f32.tf32.tf32.f32 "
    "{%0,%1,%2,%3}, {%4,%5,%6,%7}, {%8,%9}, {%0,%1,%2,%3};"
    : "+f"(d0), "+f"(d1), "+f"(d2), "+f"(d3)
    : "r"(a0), "r"(a1), "r"(a2), "r"(a3), "r"(b0), "r"(b1));
}

// m16n8k16 bf16 mma (sm_80 base ISA)
__device__ __forceinline__ void mma_bf16(float* d, const uint32_t* a, uint32_t b0, uint32_t b1){
  asm volatile(
    "mma.sync.aligned.m16n8k16.row.col.f32.bf16.bf16.f32 "
    "{%0,%1,%2,%3}, {%4,%5,%6,%7}, {%8,%9}, {%0,%1,%2,%3};"
    : "+f"(d[0]), "+f"(d[1]), "+f"(d[2]), "+f"(d[3])
    : "r"(a[0]), "r"(a[1]), "r"(a[2]), "r"(a[3]), "r"(b0), "r"(b1));
}

// ================= fused LN + 5 projections =================
#define LDX 132
#define LDW 136
#define XS_WORDS (128*LDX)
#define W_WORDS  (128*LDW)
#define PROJALL_SMEM ((XS_WORDS + 2*W_WORDS)*4)

// Shared GEMM-pair mainloop: acc1 += xs@w1, (dual) acc2 += xs@w2
__device__ __forceinline__ void gemm_pair(const uint32_t* __restrict__ xs,
                                          const uint32_t* __restrict__ w1,
                                          const uint32_t* __restrict__ w2,
                                          int wm, int wn, int gid, int tig,
                                          float acc1[2][4][4], float acc2[2][4][4],
                                          bool dual){
  const uint32_t* xa  = xs + (wm*32 + gid)*LDX + tig;
  const uint32_t* wb1 = w1 + tig*LDW + wn*32 + gid;
  const uint32_t* wb2 = w2 + tig*LDW + wn*32 + gid;
  #pragma unroll
  for (int kc=0; kc<16; kc++){
    uint32_t a[2][4];
    #pragma unroll
    for (int t=0;t<2;t++){
      const uint32_t* p = xa + t*16*LDX + kc*8;
      a[t][0] = p[0];
      a[t][1] = p[8*LDX];
      a[t][2] = p[4];
      a[t][3] = p[8*LDX + 4];
    }
    #pragma unroll
    for (int u=0;u<4;u++){
      const uint32_t* q1 = wb1 + kc*8*LDW + u*8;
      uint32_t b10 = q1[0], b11 = q1[4*LDW];
      #pragma unroll
      for (int t=0;t<2;t++)
        mma_tf32(acc1[t][u][0],acc1[t][u][1],acc1[t][u][2],acc1[t][u][3],
                 a[t][0],a[t][1],a[t][2],a[t][3], b10,b11);
      if (dual){
        const uint32_t* q2 = wb2 + kc*8*LDW + u*8;
        uint32_t b20 = q2[0], b21 = q2[4*LDW];
        #pragma unroll
        for (int t=0;t<2;t++)
          mma_tf32(acc2[t][u][0],acc2[t][u][1],acc2[t][u][2],acc2[t][u][3],
                   a[t][0],a[t][1],a[t][2],a[t][3], b20,b21);
      }
    }
  }
}

// stage one W matrix (tf32) into SMEM
__device__ __forceinline__ void stage_w(const float* __restrict__ W, uint32_t* __restrict__ w,
                                        int tid){
  #pragma unroll
  for (int it=0; it<8; ++it){
    int slot = tid + it*512;
    int r  = slot >> 5;
    int kv = slot & 31;
    float4 v = *reinterpret_cast<const float4*>(&W[r*CDIM + kv*4]);
    uint4 t; t.x=tf32_rna(v.x); t.y=tf32_rna(v.y); t.z=tf32_rna(v.z); t.w=tf32_rna(v.w);
    *reinterpret_cast<uint4*>(&w[r*LDW + kv*4]) = t;
  }
}

// epilogue: bias+sigmoid+mask -> bf16 hi/lo, SMEM transpose -> [c][row] global
__device__ __forceinline__ void epi_bf16(const float acc1[2][4][4], const float acc2[2][4][4],
    const float* __restrict__ mask, const float* __restrict__ bb1, const float* __restrict__ bb2,
    __nv_bfloat16* shi, __nv_bfloat16* slo,
    __nv_bfloat16* __restrict__ ghi, __nv_bfloat16* __restrict__ glo,
    int row0, int tid, int wm, int wn, int gid, int tig){
  #pragma unroll
  for (int t=0;t<2;t++){
    int rA = wm*32 + t*16 + gid;
    int rB = rA + 8;
    float mvA = mask[row0 + rA], mvB = mask[row0 + rB];
    #pragma unroll
    for (int u=0;u<4;u++){
      int colb = wn*32 + u*8 + 2*tig;
      float vals[4];
      vals[0] = mvA*(acc1[t][u][0]+bb1[colb  ])*sigmoidf_(acc2[t][u][0]+bb2[colb  ]);
      vals[1] = mvA*(acc1[t][u][1]+bb1[colb+1])*sigmoidf_(acc2[t][u][1]+bb2[colb+1]);
      vals[2] = mvB*(acc1[t][u][2]+bb1[colb  ])*sigmoidf_(acc2[t][u][2]+bb2[colb  ]);
      vals[3] = mvB*(acc1[t][u][3]+bb1[colb+1])*sigmoidf_(acc2[t][u][3]+bb2[colb+1]);
      int rr[4] = {rA, rA, rB, rB};
      int cc[4] = {colb, colb+1, colb, colb+1};
      #pragma unroll
      for (int q=0;q<4;q++){
        __nv_bfloat16 h = __float2bfloat16(vals[q]);
        shi[cc[q]*128 + rr[q]] = h;
        slo[cc[q]*128 + rr[q]] = __float2bfloat16(vals[q] - __bfloat162float(h));
      }
    }
  }
  __syncthreads();
  {
    int c = tid>>2, q = tid&3;
    const uint4* sh_ = reinterpret_cast<const uint4*>(shi + c*128 + q*32);
    const uint4* sl_ = reinterpret_cast<const uint4*>(slo + c*128 + q*32);
    uint4* dh = reinterpret_cast<uint4*>(ghi + (size_t)c*NROWS + row0 + q*32);
    uint4* dl = reinterpret_cast<uint4*>(glo + (size_t)c*NROWS + row0 + q*32);
    #pragma unroll
    for (int i=0;i<4;i++){ dh[i] = sh_[i]; dl[i] = sl_[i]; }
  }
  __syncthreads();
}

__global__ __launch_bounds__(512) void proj_all_kernel(
    const float* __restrict__ act, const float* __restrict__ lng, const float* __restrict__ lnb,
    const float* __restrict__ mask,
    const float* __restrict__ Wl,  const float* __restrict__ bl,
    const float* __restrict__ Wgl, const float* __restrict__ bgl,
    const float* __restrict__ Wr,  const float* __restrict__ br,
    const float* __restrict__ Wgr, const float* __restrict__ bgr,
    const float* __restrict__ Wg,  const float* __restrict__ bg,
    __nv_bfloat16* __restrict__ gLh, __nv_bfloat16* __restrict__ gLl,
    __nv_bfloat16* __restrict__ gRh, __nv_bfloat16* __restrict__ gRl,
    float* __restrict__ gate){
  extern __shared__ uint32_t sm[];
  uint32_t* xs = sm;
  uint32_t* w1 = sm + XS_WORDS;
  uint32_t* w2 = w1 + W_WORDS;
  float*    fs = reinterpret_cast<float*>(xs);
  __shared__ float mu_s[128], rs_s[128];
  int tid  = threadIdx.x;
  int row0 = blockIdx.x * 128;

  // Stage raw act tile + Wl/Wgl (tf32)
  #pragma unroll
  for (int it=0; it<8; ++it){
    int slot = tid + it*512;
    int r  = slot >> 5;
    int kv = slot & 31;
    float4 v = *reinterpret_cast<const float4*>(&act[(size_t)(row0+r)*CDIM + kv*4]);
    *reinterpret_cast<float4*>(&fs[r*LDX + kv*4]) = v;
    v = *reinterpret_cast<const float4*>(&Wl[r*CDIM + kv*4]);
    uint4 t; t.x=tf32_rna(v.x); t.y=tf32_rna(v.y); t.z=tf32_rna(v.z); t.w=tf32_rna(v.w);
    *reinterpret_cast<uint4*>(&w1[r*LDW + kv*4]) = t;
    v = *reinterpret_cast<const float4*>(&Wgl[r*CDIM + kv*4]);
    t.x=tf32_rna(v.x); t.y=tf32_rna(v.y); t.z=tf32_rna(v.z); t.w=tf32_rna(v.w);
    *reinterpret_cast<uint4*>(&w2[r*LDW + kv*4]) = t;
  }
  __syncthreads();

  // In-SMEM LayerNorm: 4 threads per row
  {
    int row = tid>>2, sub = tid&3;
    float s=0.f, s2=0.f;
    #pragma unroll
    for (int q=0;q<8;q++){
      float4 v = *reinterpret_cast<const float4*>(&fs[row*LDX + sub*32 + q*4]);
      s  += v.x+v.y+v.z+v.w;
      s2 += v.x*v.x+v.y*v.y+v.z*v.z+v.w*v.w;
    }
    s  += __shfl_xor_sync(0xffffffffu, s, 1);  s  += __shfl_xor_sync(0xffffffffu, s, 2);
    s2 += __shfl_xor_sync(0xffffffffu, s2, 1); s2 += __shfl_xor_sync(0xffffffffu, s2, 2);
    if (sub==0){
      float mu = s*(1.f/128.f);
      mu_s[row] = mu;
      rs_s[row] = rsqrtf(s2*(1.f/128.f) - mu*mu + EPSV);
    }
  }
  __syncthreads();
  // normalize + tf32 in place
  #pragma unroll
  for (int it=0; it<8; ++it){
    int slot = tid + it*512;
    int r  = slot >> 5;
    int kv = slot & 31;
    int c0 = kv*4;
    float mu = mu_s[r], rs = rs_s[r];
    float4 v = *reinterpret_cast<const float4*>(&fs[r*LDX + c0]);
    uint4 t;
    t.x = tf32_rna((v.x-mu)*rs*lng[c0+0] + lnb[c0+0]);
    t.y = tf32_rna((v.y-mu)*rs*lng[c0+1] + lnb[c0+1]);
    t.z = tf32_rna((v.z-mu)*rs*lng[c0+2] + lnb[c0+2]);
    t.w = tf32_rna((v.w-mu)*rs*lng[c0+3] + lnb[c0+3]);
    *reinterpret_cast<uint4*>(&xs[r*LDX + c0]) = t;
  }
  __syncthreads();

  int lane = tid&31, wid = tid>>5;
  int wm = wid>>2, wn = wid&3;
  int gid = lane>>2, tig = lane&3;

  float acc1[2][4][4], acc2[2][4][4];
  __nv_bfloat16* shi = reinterpret_cast<__nv_bfloat16*>(w1);
  __nv_bfloat16* slo = reinterpret_cast<__nv_bfloat16*>(w2);

  // ---- GEMM 1: left ----
  #pragma unroll
  for (int t=0;t<2;t++)
    #pragma unroll
    for (int u=0;u<4;u++)
      #pragma unroll
      for (int r=0;r<4;r++){ acc1[t][u][r]=0.f; acc2[t][u][r]=0.f; }
  gemm_pair(xs, w1, w2, wm, wn, gid, tig, acc1, acc2, true);
  __syncthreads();
  epi_bf16(acc1, acc2, mask, bl, bgl, shi, slo, gLh, gLl, row0, tid, wm, wn, gid, tig);

  // ---- GEMM 2: right ----
  stage_w(Wr,  w1, tid);
  stage_w(Wgr, w2, tid);
  __syncthreads();
  #pragma unroll
  for (int t=0;t<2;t++)
    #pragma unroll
    for (int u=0;u<4;u++)
      #pragma unroll
      for (int r=0;r<4;r++){ acc1[t][u][r]=0.f; acc2[t][u][r]=0.f; }
  gemm_pair(xs, w1, w2, wm, wn, gid, tig, acc1, acc2, true);
  __syncthreads();
  epi_bf16(acc1, acc2, mask, br, bgr, shi, slo, gRh, gRl, row0, tid, wm, wn, gid, tig);

  // ---- GEMM 3: gate ----
  stage_w(Wg, w1, tid);
  __syncthreads();
  #pragma unroll
  for (int t=0;t<2;t++)
    #pragma unroll
    for (int u=0;u<4;u++)
      #pragma unroll
      for (int r=0;r<4;r++) acc1[t][u][r]=0.f;
  gemm_pair(xs, w1, w1, wm, wn, gid, tig, acc1, acc2, false);
  #pragma unroll
  for (int t=0;t<2;t++){
    int rowA = row0 + wm*32 + t*16 + gid;
    int rowB = rowA + 8;
    #pragma unroll
    for (int u=0;u<4;u++){
      int colb = wn*32 + u*8 + 2*tig;
      float b0 = bg[colb], b1 = bg[colb+1];
      float2 oA, oB;
      oA.x = sigmoidf_(acc1[t][u][0]+b0);
      oA.y = sigmoidf_(acc1[t][u][1]+b1);
      oB.x = sigmoidf_(acc1[t][u][2]+b0);
      oB.y = sigmoidf_(acc1[t][u][3]+b1);
      *reinterpret_cast<float2*>(&gate[(size_t)rowA*CDIM + colb]) = oA;
      *reinterpret_cast<float2*>(&gate[(size_t)rowB*CDIM + colb]) = oB;
    }
  }
}

// ============== Stage 3: per-channel GEMM via bf16-split mma ==============
#define TRI_LDS 72
#define TRI_SMEM ((64*TRI_LDS*2 + 128*TRI_LDS*2)*2)
__global__ __launch_bounds__(256) void tri_kernel(){
  extern __shared__ __nv_bfloat16 smb[];
  __nv_bfloat16* Lhi = smb;
  __nv_bfloat16* Llo = smb + 64*TRI_LDS;
  __nv_bfloat16* Rhi = smb + 2*64*TRI_LDS;
  __nv_bfloat16* Rlo = Rhi + 128*TRI_LDS;
  int tid = threadIdx.x;
  int c  = blockIdx.z;
  int i0 = blockIdx.x * 64;
  int j0 = blockIdx.y * 128;
  const __nv_bfloat16* gLh = g_Lhi + (size_t)c*NROWS;
  const __nv_bfloat16* gLl = g_Llo + (size_t)c*NROWS;
  const __nv_bfloat16* gRh = g_Rhi + (size_t)c*NROWS;
  const __nv_bfloat16* gRl = g_Rlo + (size_t)c*NROWS;

  int lane = tid&31, wid = tid>>5;
  int wm = wid>>2, wn = wid&3;
  int gid = lane>>2, tig = lane&3;

  float acc[2][4][4];
  #pragma unroll
  for (int t=0;t<2;t++)
    #pragma unroll
    for (int u=0;u<4;u++)
      #pragma unroll
      for (int r=0;r<4;r++) acc[t][u][r]=0.f;

  for (int kc=0; kc<NTOK; kc+=64){
    __syncthreads();
    #pragma unroll
    for (int it=0; it<2; it++){
      int slot = tid + it*256;
      int r = slot>>3, seg = slot&7;
      size_t go = (size_t)(i0+r)*NTOK + kc + seg*8;
      *reinterpret_cast<uint4*>(&Lhi[r*TRI_LDS + seg*8]) = *reinterpret_cast<const uint4*>(&gLh[go]);
      *reinterpret_cast<uint4*>(&Llo[r*TRI_LDS + seg*8]) = *reinterpret_cast<const uint4*>(&gLl[go]);
    }
    #pragma unroll
    for (int it=0; it<4; it++){
      int slot = tid + it*256;
      int r = slot>>3, seg = slot&7;
      size_t go = (size_t)(j0+r)*NTOK + kc + seg*8;
      *reinterpret_cast<uint4*>(&Rhi[r*TRI_LDS + seg*8]) = *reinterpret_cast<const uint4*>(&gRh[go]);
      *reinterpret_cast<uint4*>(&Rlo[r*TRI_LDS + seg*8]) = *reinterpret_cast<const uint4*>(&gRl[go]);
    }
    __syncthreads();

    #pragma unroll
    for (int ks=0; ks<4; ks++){
      int ko = ks*16;
      uint32_t ah[2][4], al[2][4];
      #pragma unroll
      for (int t=0;t<2;t++){
        int row = wm*32 + t*16 + gid;
        int base = row*TRI_LDS + ko + 2*tig;
        ah[t][0] = *reinterpret_cast<const uint32_t*>(&Lhi[base]);
        ah[t][1] = *reinterpret_cast<const uint32_t*>(&Lhi[base + 8*TRI_LDS]);
        ah[t][2] = *reinterpret_cast<const uint32_t*>(&Lhi[base + 8]);
        ah[t][3] = *reinterpret_cast<const uint32_t*>(&Lhi[base + 8*TRI_LDS + 8]);
        al[t][0] = *reinterpret_cast<const uint32_t*>(&Llo[base]);
        al[t][1] = *reinterpret_cast<const uint32_t*>(&Llo[base + 8*TRI_LDS]);
        al[t][2] = *reinterpret_cast<const uint32_t*>(&Llo[base + 8]);
        al[t][3] = *reinterpret_cast<const uint32_t*>(&Llo[base + 8*TRI_LDS + 8]);
      }
      #pragma unroll
      for (int u=0;u<4;u++){
        int jrow = wn*32 + u*8 + gid;
        int bb = jrow*TRI_LDS + ko + 2*tig;
        uint32_t bh0 = *reinterpret_cast<const uint32_t*>(&Rhi[bb]);
        uint32_t bh1 = *reinterpret_cast<const uint32_t*>(&Rhi[bb + 8]);
        uint32_t bl0 = *reinterpret_cast<const uint32_t*>(&Rlo[bb]);
        uint32_t bl1 = *reinterpret_cast<const uint32_t*>(&Rlo[bb + 8]);
        #pragma unroll
        for (int t=0;t<2;t++){
          mma_bf16(acc[t][u], ah[t], bh0, bh1);
          mma_bf16(acc[t][u], ah[t], bl0, bl1);
          mma_bf16(acc[t][u], al[t], bh0, bh1);
        }
      }
    }
  }

  float* To = g_tri + (size_t)c*NROWS;
  #pragma unroll
  for (int t=0;t<2;t++){
    int iA = i0 + wm*32 + t*16 + gid;
    int iB = iA + 8;
    #pragma unroll
    for (int u=0;u<4;u++){
      int j = j0 + wn*32 + u*8 + 2*tig;
      float2 vA = {acc[t][u][0], acc[t][u][1]};
      float2 vB = {acc[t][u][2], acc[t][u][3]};
      *reinterpret_cast<float2*>(&To[(size_t)iA*NTOK + j]) = vA;
      *reinterpret_cast<float2*>(&To[(size_t)iB*NTOK + j]) = vB;
    }
  }
}

// ============== Stage 4: LN(tri) @ Wo + bo, * gate (tf32 mma) ==============
#define LDT 129
#define FINAL_SMEM ((128*LDT + XS_WORDS + W_WORDS)*4)
__global__ __launch_bounds__(512) void final_kernel(const float* __restrict__ cg,
                                                    const float* __restrict__ cb,
                                                    const float* __restrict__ Wo,
                                                    const float* __restrict__ bo,
                                                    float* __restrict__ out){
  extern __shared__ uint32_t sm[];
  float*    T  = reinterpret_cast<float*>(sm);
  uint32_t* xs = sm + 128*LDT;
  uint32_t* w  = xs + XS_WORDS;
  __shared__ float p1[4][128], p2[4][128], mu_s[128], rs_s[128];
  int tid  = threadIdx.x;
  int row0 = blockIdx.x * 128;

  #pragma unroll
  for (int it=0; it<8; ++it){
    int slot = tid + it*512;
    int cch = slot >> 5;
    int v4  = slot & 31;
    float4 v = *reinterpret_cast<const float4*>(&g_tri[(size_t)cch*NROWS + row0 + v4*4]);
    T[cch*LDT + v4*4 + 0] = v.x;
    T[cch*LDT + v4*4 + 1] = v.y;
    T[cch*LDT + v4*4 + 2] = v.z;
    T[cch*LDT + v4*4 + 3] = v.w;
    v = *reinterpret_cast<const float4*>(&Wo[cch*CDIM + v4*4]);
    uint4 t; t.x=tf32_rna(v.x); t.y=tf32_rna(v.y); t.z=tf32_rna(v.z); t.w=tf32_rna(v.w);
    *reinterpret_cast<uint4*>(&w[cch*LDW + v4*4]) = t;
  }
  __syncthreads();

  {
    int ij = tid & 127, pp = tid >> 7;
    float s=0.f, s2=0.f;
    #pragma unroll
    for (int k=0;k<32;k++){
      float v = T[(pp*32+k)*LDT + ij];
      s += v; s2 += v*v;
    }
    p1[pp][ij] = s; p2[pp][ij] = s2;
  }
  __syncthreads();
  if (tid < 128){
    float s  = p1[0][tid]+p1[1][tid]+p1[2][tid]+p1[3][tid];
    float s2 = p2[0][tid]+p2[1][tid]+p2[2][tid]+p2[3][tid];
    float mu = s*(1.f/128.f);
    mu_s[tid] = mu;
    rs_s[tid] = rsqrtf(s2*(1.f/128.f) - mu*mu + EPSV);
  }
  __syncthreads();

  #pragma unroll
  for (int it=0; it<8; ++it){
    int slot = tid + it*512;
    int r  = slot & 127;
    int cq = slot >> 7;
    float mu = mu_s[r], rs = rs_s[r];
    uint4 t;
    {
      int c0 = cq*4;
      float v0 = (T[(c0+0)*LDT + r]-mu)*rs*cg[c0+0] + cb[c0+0];
      float v1 = (T[(c0+1)*LDT + r]-mu)*rs*cg[c0+1] + cb[c0+1];
      float v2 = (T[(c0+2)*LDT + r]-mu)*rs*cg[c0+2] + cb[c0+2];
      float v3 = (T[(c0+3)*LDT + r]-mu)*rs*cg[c0+3] + cb[c0+3];
      t.x=tf32_rna(v0); t.y=tf32_rna(v1); t.z=tf32_rna(v2); t.w=tf32_rna(v3);
    }
    *reinterpret_cast<uint4*>(&xs[r*LDX + cq*4]) = t;
  }
  __syncthreads();

  int lane = tid&31, wid = tid>>5;
  int wm = wid>>2, wn = wid&3;
  int gid = lane>>2, tig = lane&3;

  float acc[2][4][4], accd[2][4][4];
  #pragma unroll
  for (int t=0;t<2;t++)
    #pragma unroll
    for (int u=0;u<4;u++)
      #pragma unroll
      for (int r=0;r<4;r++) acc[t][u][r]=0.f;

  gemm_pair(xs, w, w, wm, wn, gid, tig, acc, accd, false);

  #pragma unroll
  for (int t=0;t<2;t++){
    int rowA = row0 + wm*32 + t*16 + gid;
    int rowB = rowA + 8;
    #pragma unroll
    for (int u=0;u<4;u++){
      int colb = wn*32 + u*8 + 2*tig;
      float bo0 = bo[colb], bo1 = bo[colb+1];
      float2 gA = *reinterpret_cast<const float2*>(&g_gate[(size_t)rowA*CDIM + colb]);
      float2 gB = *reinterpret_cast<const float2*>(&g_gate[(size_t)rowB*CDIM + colb]);
      float2 oA, oB;
      oA.x = (acc[t][u][0]+bo0)*gA.x;
      oA.y = (acc[t][u][1]+bo1)*gA.y;
      oB.x = (acc[t][u][2]+bo0)*gB.x;
      oB.y = (acc[t][u][3]+bo1)*gB.y;
      *reinterpret_cast<float2*>(&out[(size_t)rowA*CDIM + colb]) = oA;
      *reinterpret_cast<float2*>(&out[(size_t)rowB*CDIM + colb]) = oB;
    }
  }
}

extern "C" void kernel_launch(void* const* d_in, const int* in_sizes, int n_in,
                              void* d_out, int out_size) {
  const float* act  = (const float*)d_in[0];
  const float* mask = (const float*)d_in[1];
  const float* ln_g = (const float*)d_in[2];
  const float* ln_b = (const float*)d_in[3];
  const float* Wl   = (const float*)d_in[4];
  const float* bl   = (const float*)d_in[5];
  const float* Wr   = (const float*)d_in[6];
  const float* br   = (const float*)d_in[7];
  const float* Wgl  = (const float*)d_in[8];
  const float* bgl  = (const float*)d_in[9];
  const float* Wgr  = (const float*)d_in[10];
  const float* bgr  = (const float*)d_in[11];
  const float* cg   = (const float*)d_in[12];
  const float* cb   = (const float*)d_in[13];
  const float* Wo   = (const float*)d_in[14];
  const float* bo   = (const float*)d_in[15];
  const float* Wg   = (const float*)d_in[16];
  const float* bg   = (const float*)d_in[17];
  float* out = (float*)d_out;

  __nv_bfloat16 *dLh=nullptr, *dLl=nullptr, *dRh=nullptr, *dRl=nullptr;
  float *dGate=nullptr;
  cudaGetSymbolAddress((void**)&dLh, g_Lhi);
  cudaGetSymbolAddress((void**)&dLl, g_Llo);
  cudaGetSymbolAddress((void**)&dRh, g_Rhi);
  cudaGetSymbolAddress((void**)&dRl, g_Rlo);
  cudaGetSymbolAddress((void**)&dGate, g_gate);

  cudaFuncSetAttribute(proj_all_kernel, cudaFuncAttributeMaxDynamicSharedMemorySize, PROJALL_SMEM);
  cudaFuncSetAttribute(tri_kernel,      cudaFuncAttributeMaxDynamicSharedMemorySize, TRI_SMEM);
  cudaFuncSetAttribute(final_kernel,    cudaFuncAttributeMaxDynamicSharedMemorySize, FINAL_SMEM);

  proj_all_kernel<<<NROWS/128, 512, PROJALL_SMEM>>>(act, ln_g, ln_b, mask,
      Wl, bl, Wgl, bgl, Wr, br, Wgr, bgr, Wg, bg,
      dLh, dLl, dRh, dRl, dGate);
  tri_kernel<<<dim3(NTOK/64, NTOK/128, CDIM), 256, TRI_SMEM>>>();
  final_kernel<<<NROWS/128, 512, FINAL_SMEM>>>(cg, cb, Wo, bo, out);
}

// round 7
// speedup vs baseline: 3.8055x; 1.0688x over previous
#include <cuda_runtime.h>
#include <cuda_bf16.h>
#include <cstdint>
#include <math.h>

#define NTOK 384
#define CDIM 128
#define NROWS (NTOK*NTOK)   /* 147456 */
#define EPSV 1e-5f

// Scratch (no cudaMalloc allowed)
__device__ float g_gate[(size_t)NROWS*CDIM];
__device__ float g_tri [(size_t)NROWS*CDIM];           // [c][i*384+j]
__device__ __nv_bfloat16 g_Lhi[(size_t)CDIM*NROWS];    // [c][i*384+k]
__device__ __nv_bfloat16 g_Llo[(size_t)CDIM*NROWS];
__device__ __nv_bfloat16 g_Rhi[(size_t)CDIM*NROWS];    // [c][j*384+k]
__device__ __nv_bfloat16 g_Rlo[(size_t)CDIM*NROWS];

__device__ __forceinline__ float sigmoidf_(float z){ return 1.f/(1.f+expf(-z)); }

__device__ __forceinline__ uint32_t tf32_rna(float f){
  uint32_t r; asm("cvt.rna.tf32.f32 %0, %1;" : "=r"(r) : "f"(f)); return r;
}
__device__ __forceinline__ uint32_t prmt_(uint32_t a, uint32_t b, uint32_t s){
  uint32_t d; asm("prmt.b32 %0,%1,%2,%3;" : "=r"(d) : "r"(a), "r"(b), "r"(s)); return d;
}
__device__ __forceinline__ uint32_t pack_hilo(float v){
  __nv_bfloat16 h = __float2bfloat16(v);
  float rem = v - __bfloat162float(h);
  __nv_bfloat16 l = __float2bfloat16(rem);
  uint16_t hb = *reinterpret_cast<uint16_t*>(&h);
  uint16_t lb = *reinterpret_cast<uint16_t*>(&l);
  return (uint32_t)hb | ((uint32_t)lb << 16);
}

// m16n8k8 tf32 mma (sm_80 base ISA)
__device__ __forceinline__ void mma_tf32(float& d0, float& d1, float& d2, float& d3,
                                         uint32_t a0, uint32_t a1, uint32_t a2, uint32_t a3,
                                         uint32_t b0, uint32_t b1){
  asm volatile(
    "mma.sync.aligned.m16n8k8.row.col.f32.tf32.tf32.f32 "
    "{%0,%1,%2,%3}, {%4,%5,%6,%7}, {%8,%9}, {%0,%1,%2,%3};"
    : "+f"(d0), "+f"(d1), "+f"(d2), "+f"(d3)
    : "r"(a0), "r"(a1), "r"(a2), "r"(a3), "r"(b0), "r"(b1));
}

// m16n8k16 bf16 mma (sm_80 base ISA)
__device__ __forceinline__ void mma_bf16(float* d, const uint32_t* a, uint32_t b0, uint32_t b1){
  asm volatile(
    "mma.sync.aligned.m16n8k16.row.col.f32.bf16.bf16.f32 "
    "{%0,%1,%2,%3}, {%4,%5,%6,%7}, {%8,%9}, {%0,%1,%2,%3};"
    : "+f"(d[0]), "+f"(d[1]), "+f"(d[2]), "+f"(d[3])
    : "r"(a[0]), "r"(a[1]), "r"(a[2]), "r"(a[3]), "r"(b0), "r"(b1));
}

// ================= fused LN + 5 projections =================
#define LDX 132
#define LDW 136
#define LDE 132
#define XS_WORDS (128*LDX)
#define W_WORDS  (128*LDW)
#define EBUF_WORDS (32*LDE)
#define PROJALL_SMEM ((XS_WORDS + 2*W_WORDS + EBUF_WORDS)*4)

// GEMM-pair mainloop: acc1 += xs@w1, (dual) acc2 += xs@w2
__device__ __forceinline__ void gemm_pair(const uint32_t* __restrict__ xs,
                                          const uint32_t* __restrict__ w1,
                                          const uint32_t* __restrict__ w2,
                                          int wm, int wn, int gid, int tig,
                                          float acc1[2][4][4], float acc2[2][4][4],
                                          bool dual){
  const uint32_t* xa  = xs + (wm*32 + gid)*LDX + tig;
  const uint32_t* wb1 = w1 + tig*LDW + wn*32 + gid;
  const uint32_t* wb2 = w2 + tig*LDW + wn*32 + gid;
  #pragma unroll
  for (int kc=0; kc<16; kc++){
    uint32_t a[2][4];
    #pragma unroll
    for (int t=0;t<2;t++){
      const uint32_t* p = xa + t*16*LDX + kc*8;
      a[t][0] = p[0];
      a[t][1] = p[8*LDX];
      a[t][2] = p[4];
      a[t][3] = p[8*LDX + 4];
    }
    #pragma unroll
    for (int u=0;u<4;u++){
      const uint32_t* q1 = wb1 + kc*8*LDW + u*8;
      uint32_t b10 = q1[0], b11 = q1[4*LDW];
      #pragma unroll
      for (int t=0;t<2;t++)
        mma_tf32(acc1[t][u][0],acc1[t][u][1],acc1[t][u][2],acc1[t][u][3],
                 a[t][0],a[t][1],a[t][2],a[t][3], b10,b11);
      if (dual){
        const uint32_t* q2 = wb2 + kc*8*LDW + u*8;
        uint32_t b20 = q2[0], b21 = q2[4*LDW];
        #pragma unroll
        for (int t=0;t<2;t++)
          mma_tf32(acc2[t][u][0],acc2[t][u][1],acc2[t][u][2],acc2[t][u][3],
                   a[t][0],a[t][1],a[t][2],a[t][3], b20,b21);
      }
    }
  }
}

// LDG one 128x128 W into registers (raw fp32 bits)
__device__ __forceinline__ void ldgW(const float* __restrict__ W, int tid, uint4 w[8]){
  #pragma unroll
  for (int it=0; it<8; ++it){
    int slot = tid + it*512;
    int r  = slot >> 5;
    int kv = slot & 31;
    w[it] = *reinterpret_cast<const uint4*>(&W[r*CDIM + kv*4]);
  }
}
// cvt tf32 + STS into a W smem buffer
__device__ __forceinline__ void stsW(const uint4 w[8], int tid, uint32_t* __restrict__ dst){
  #pragma unroll
  for (int it=0; it<8; ++it){
    int slot = tid + it*512;
    int r  = slot >> 5;
    int kv = slot & 31;
    float4 v = *reinterpret_cast<const float4*>(&w[it]);
    uint4 t; t.x=tf32_rna(v.x); t.y=tf32_rna(v.y); t.z=tf32_rna(v.z); t.w=tf32_rna(v.w);
    *reinterpret_cast<uint4*>(&dst[r*LDW + kv*4]) = t;
  }
}

// bias+sigmoid+mask -> (hi,lo) packed words
__device__ __forceinline__ void compute_pk(const float acc1[2][4][4], const float acc2[2][4][4],
    const float* __restrict__ mask, const float* __restrict__ bb1, const float* __restrict__ bb2,
    int row0, int wm, int wn, int gid, int tig, uint32_t pk[32]){
  #pragma unroll
  for (int t=0;t<2;t++){
    int rA = wm*32 + t*16 + gid;
    int rB = rA + 8;
    float mvA = mask[row0 + rA], mvB = mask[row0 + rB];
    #pragma unroll
    for (int u=0;u<4;u++){
      int colb = wn*32 + u*8 + 2*tig;
      float2 b1v = *reinterpret_cast<const float2*>(&bb1[colb]);
      float2 b2v = *reinterpret_cast<const float2*>(&bb2[colb]);
      float v0 = mvA*(acc1[t][u][0]+b1v.x)*sigmoidf_(acc2[t][u][0]+b2v.x);
      float v1 = mvA*(acc1[t][u][1]+b1v.y)*sigmoidf_(acc2[t][u][1]+b2v.y);
      float v2 = mvB*(acc1[t][u][2]+b1v.x)*sigmoidf_(acc2[t][u][2]+b2v.x);
      float v3 = mvB*(acc1[t][u][3]+b1v.y)*sigmoidf_(acc2[t][u][3]+b2v.y);
      pk[t*16+u*4+0] = pack_hilo(v0);
      pk[t*16+u*4+1] = pack_hilo(v1);
      pk[t*16+u*4+2] = pack_hilo(v2);
      pk[t*16+u*4+3] = pack_hilo(v3);
    }
  }
}

// 4-pass packed epilogue store: SMEM transpose (conflict-free) + PRMT split + coalesced STG
__device__ __forceinline__ void epi_store(const uint32_t pk[32], uint32_t* __restrict__ ebuf,
    __nv_bfloat16* __restrict__ ghi, __nv_bfloat16* __restrict__ glo,
    int row0, int tid, int wm, int wn, int gid, int tig){
  #pragma unroll
  for (int p=0;p<4;p++){
    if (wn == p){
      #pragma unroll
      for (int t=0;t<2;t++){
        int rA = wm*32 + t*16 + gid;
        int rB = rA + 8;
        #pragma unroll
        for (int u=0;u<4;u++){
          int cl = u*8 + 2*tig;
          ebuf[ cl   *LDE + rA] = pk[t*16+u*4+0];
          ebuf[(cl+1)*LDE + rA] = pk[t*16+u*4+1];
          ebuf[ cl   *LDE + rB] = pk[t*16+u*4+2];
          ebuf[(cl+1)*LDE + rB] = pk[t*16+u*4+3];
        }
      }
    }
    __syncthreads();
    {
      int cl = tid >> 4;
      int rb = tid & 15;
      #pragma unroll
      for (int h=0; h<2; h++){
        int rq = rb + 16*h;
        uint4 w = *reinterpret_cast<const uint4*>(&ebuf[cl*LDE + rq*4]);
        uint32_t hi01 = prmt_(w.x, w.y, 0x5410u);
        uint32_t hi23 = prmt_(w.z, w.w, 0x5410u);
        uint32_t lo01 = prmt_(w.x, w.y, 0x7632u);
        uint32_t lo23 = prmt_(w.z, w.w, 0x7632u);
        size_t base = (size_t)(p*32 + cl)*NROWS + row0 + rq*4;
        *reinterpret_cast<uint2*>(&ghi[base]) = make_uint2(hi01, hi23);
        *reinterpret_cast<uint2*>(&glo[base]) = make_uint2(lo01, lo23);
      }
    }
    __syncthreads();
  }
}

__global__ __launch_bounds__(512) void proj_all_kernel(
    const float* __restrict__ act, const float* __restrict__ lng, const float* __restrict__ lnb,
    const float* __restrict__ mask,
    const float* __restrict__ Wl,  const float* __restrict__ bl,
    const float* __restrict__ Wgl, const float* __restrict__ bgl,
    const float* __restrict__ Wr,  const float* __restrict__ br,
    const float* __restrict__ Wgr, const float* __restrict__ bgr,
    const float* __restrict__ Wg,  const float* __restrict__ bg,
    __nv_bfloat16* __restrict__ gLh, __nv_bfloat16* __restrict__ gLl,
    __nv_bfloat16* __restrict__ gRh, __nv_bfloat16* __restrict__ gRl,
    float* __restrict__ gate){
  extern __shared__ uint32_t sm[];
  uint32_t* xs   = sm;
  uint32_t* w1   = sm + XS_WORDS;
  uint32_t* w2   = w1 + W_WORDS;
  uint32_t* ebuf = w2 + W_WORDS;
  int tid  = threadIdx.x;
  int row0 = blockIdx.x * 128;
  int kv   = tid & 31;

  // ---- fused staging: act LDG + in-register LN + tf32 STS; W1/W2 via reg roundtrip ----
  {
    uint4 va[8];
    #pragma unroll
    for (int it=0; it<8; ++it){
      int r = (tid>>5) + it*16;
      va[it] = *reinterpret_cast<const uint4*>(&act[(size_t)(row0+r)*CDIM + kv*4]);
    }
    uint4 wA[8], wB[8];
    ldgW(Wl,  tid, wA);
    ldgW(Wgl, tid, wB);
    float4 g4 = *reinterpret_cast<const float4*>(&lng[kv*4]);
    float4 b4 = *reinterpret_cast<const float4*>(&lnb[kv*4]);
    #pragma unroll
    for (int it=0; it<8; ++it){
      int r = (tid>>5) + it*16;
      float4 v = *reinterpret_cast<const float4*>(&va[it]);
      float s  = v.x + v.y + v.z + v.w;
      float s2 = v.x*v.x + v.y*v.y + v.z*v.z + v.w*v.w;
      #pragma unroll
      for (int off=16; off>0; off>>=1){
        s  += __shfl_xor_sync(0xffffffffu, s,  off);
        s2 += __shfl_xor_sync(0xffffffffu, s2, off);
      }
      float mu = s * (1.f/128.f);
      float rs = rsqrtf(s2*(1.f/128.f) - mu*mu + EPSV);
      uint4 t;
      t.x = tf32_rna((v.x-mu)*rs*g4.x + b4.x);
      t.y = tf32_rna((v.y-mu)*rs*g4.y + b4.y);
      t.z = tf32_rna((v.z-mu)*rs*g4.z + b4.z);
      t.w = tf32_rna((v.w-mu)*rs*g4.w + b4.w);
      *reinterpret_cast<uint4*>(&xs[r*LDX + kv*4]) = t;
    }
    stsW(wA, tid, w1);
    stsW(wB, tid, w2);
  }
  __syncthreads();

  int lane = tid&31, wid = tid>>5;
  int wm = wid>>2, wn = wid&3;
  int gid = lane>>2, tig = lane&3;

  float acc1[2][4][4], acc2[2][4][4];
  uint32_t pk[32];

  // ---- GEMM 1: left (dual) ----
  #pragma unroll
  for (int t=0;t<2;t++)
    #pragma unroll
    for (int u=0;u<4;u++)
      #pragma unroll
      for (int r=0;r<4;r++){ acc1[t][u][r]=0.f; acc2[t][u][r]=0.f; }
  gemm_pair(xs, w1, w2, wm, wn, gid, tig, acc1, acc2, true);
  compute_pk(acc1, acc2, mask, bl, bgl, row0, wm, wn, gid, tig, pk);
  {
    uint4 wA[8], wB[8];
    ldgW(Wr,  tid, wA);            // prefetch next W pair; completes under epilogue
    ldgW(Wgr, tid, wB);
    epi_store(pk, ebuf, gLh, gLl, row0, tid, wm, wn, gid, tig);
    stsW(wA, tid, w1);
    stsW(wB, tid, w2);
  }
  __syncthreads();

  // ---- GEMM 2: right (dual) ----
  #pragma unroll
  for (int t=0;t<2;t++)
    #pragma unroll
    for (int u=0;u<4;u++)
      #pragma unroll
      for (int r=0;r<4;r++){ acc1[t][u][r]=0.f; acc2[t][u][r]=0.f; }
  gemm_pair(xs, w1, w2, wm, wn, gid, tig, acc1, acc2, true);
  compute_pk(acc1, acc2, mask, br, bgr, row0, wm, wn, gid, tig, pk);
  {
    uint4 wA[8];
    ldgW(Wg, tid, wA);             // prefetch gate W under epilogue
    epi_store(pk, ebuf, gRh, gRl, row0, tid, wm, wn, gid, tig);
    stsW(wA, tid, w1);
  }
  __syncthreads();

  // ---- GEMM 3: gate (single) ----
  #pragma unroll
  for (int t=0;t<2;t++)
    #pragma unroll
    for (int u=0;u<4;u++)
      #pragma unroll
      for (int r=0;r<4;r++) acc1[t][u][r]=0.f;
  gemm_pair(xs, w1, w1, wm, wn, gid, tig, acc1, acc2, false);
  #pragma unroll
  for (int t=0;t<2;t++){
    int rowA = row0 + wm*32 + t*16 + gid;
    int rowB = rowA + 8;
    #pragma unroll
    for (int u=0;u<4;u++){
      int colb = wn*32 + u*8 + 2*tig;
      float b0 = bg[colb], b1 = bg[colb+1];
      float2 oA, oB;
      oA.x = sigmoidf_(acc1[t][u][0]+b0);
      oA.y = sigmoidf_(acc1[t][u][1]+b1);
      oB.x = sigmoidf_(acc1[t][u][2]+b0);
      oB.y = sigmoidf_(acc1[t][u][3]+b1);
      *reinterpret_cast<float2*>(&gate[(size_t)rowA*CDIM + colb]) = oA;
      *reinterpret_cast<float2*>(&gate[(size_t)rowB*CDIM + colb]) = oB;
    }
  }
}

// ============== Stage 3: per-channel GEMM via bf16-split mma ==============
#define TRI_LDS 72
#define TRI_SMEM ((64*TRI_LDS*2 + 128*TRI_LDS*2)*2)
__global__ __launch_bounds__(256) void tri_kernel(){
  extern __shared__ __nv_bfloat16 smb[];
  __nv_bfloat16* Lhi = smb;
  __nv_bfloat16* Llo = smb + 64*TRI_LDS;
  __nv_bfloat16* Rhi = smb + 2*64*TRI_LDS;
  __nv_bfloat16* Rlo = Rhi + 128*TRI_LDS;
  int tid = threadIdx.x;
  int c  = blockIdx.z;
  int i0 = blockIdx.x * 64;
  int j0 = blockIdx.y * 128;
  const __nv_bfloat16* gLh = g_Lhi + (size_t)c*NROWS;
  const __nv_bfloat16* gLl = g_Llo + (size_t)c*NROWS;
  const __nv_bfloat16* gRh = g_Rhi + (size_t)c*NROWS;
  const __nv_bfloat16* gRl = g_Rlo + (size_t)c*NROWS;

  int lane = tid&31, wid = tid>>5;
  int wm = wid>>2, wn = wid&3;
  int gid = lane>>2, tig = lane&3;

  float acc[2][4][4];
  #pragma unroll
  for (int t=0;t<2;t++)
    #pragma unroll
    for (int u=0;u<4;u++)
      #pragma unroll
      for (int r=0;r<4;r++) acc[t][u][r]=0.f;

  for (int kc=0; kc<NTOK; kc+=64){
    __syncthreads();
    #pragma unroll
    for (int it=0; it<2; it++){
      int slot = tid + it*256;
      int r = slot>>3, seg = slot&7;
      size_t go = (size_t)(i0+r)*NTOK + kc + seg*8;
      *reinterpret_cast<uint4*>(&Lhi[r*TRI_LDS + seg*8]) = *reinterpret_cast<const uint4*>(&gLh[go]);
      *reinterpret_cast<uint4*>(&Llo[r*TRI_LDS + seg*8]) = *reinterpret_cast<const uint4*>(&gLl[go]);
    }
    #pragma unroll
    for (int it=0; it<4; it++){
      int slot = tid + it*256;
      int r = slot>>3, seg = slot&7;
      size_t go = (size_t)(j0+r)*NTOK + kc + seg*8;
      *reinterpret_cast<uint4*>(&Rhi[r*TRI_LDS + seg*8]) = *reinterpret_cast<const uint4*>(&gRh[go]);
      *reinterpret_cast<uint4*>(&Rlo[r*TRI_LDS + seg*8]) = *reinterpret_cast<const uint4*>(&gRl[go]);
    }
    __syncthreads();

    #pragma unroll
    for (int ks=0; ks<4; ks++){
      int ko = ks*16;
      uint32_t ah[2][4], al[2][4];
      #pragma unroll
      for (int t=0;t<2;t++){
        int row = wm*32 + t*16 + gid;
        int base = row*TRI_LDS + ko + 2*tig;
        ah[t][0] = *reinterpret_cast<const uint32_t*>(&Lhi[base]);
        ah[t][1] = *reinterpret_cast<const uint32_t*>(&Lhi[base + 8*TRI_LDS]);
        ah[t][2] = *reinterpret_cast<const uint32_t*>(&Lhi[base + 8]);
        ah[t][3] = *reinterpret_cast<const uint32_t*>(&Lhi[base + 8*TRI_LDS + 8]);
        al[t][0] = *reinterpret_cast<const uint32_t*>(&Llo[base]);
        al[t][1] = *reinterpret_cast<const uint32_t*>(&Llo[base + 8*TRI_LDS]);
        al[t][2] = *reinterpret_cast<const uint32_t*>(&Llo[base + 8]);
        al[t][3] = *reinterpret_cast<const uint32_t*>(&Llo[base + 8*TRI_LDS + 8]);
      }
      #pragma unroll
      for (int u=0;u<4;u++){
        int jrow = wn*32 + u*8 + gid;
        int bb = jrow*TRI_LDS + ko + 2*tig;
        uint32_t bh0 = *reinterpret_cast<const uint32_t*>(&Rhi[bb]);
        uint32_t bh1 = *reinterpret_cast<const uint32_t*>(&Rhi[bb + 8]);
        uint32_t bl0 = *reinterpret_cast<const uint32_t*>(&Rlo[bb]);
        uint32_t bl1 = *reinterpret_cast<const uint32_t*>(&Rlo[bb + 8]);
        #pragma unroll
        for (int t=0;t<2;t++){
          mma_bf16(acc[t][u], ah[t], bh0, bh1);
          mma_bf16(acc[t][u], ah[t], bl0, bl1);
          mma_bf16(acc[t][u], al[t], bh0, bh1);
        }
      }
    }
  }

  float* To = g_tri + (size_t)c*NROWS;
  #pragma unroll
  for (int t=0;t<2;t++){
    int iA = i0 + wm*32 + t*16 + gid;
    int iB = iA + 8;
    #pragma unroll
    for (int u=0;u<4;u++){
      int j = j0 + wn*32 + u*8 + 2*tig;
      float2 vA = {acc[t][u][0], acc[t][u][1]};
      float2 vB = {acc[t][u][2], acc[t][u][3]};
      *reinterpret_cast<float2*>(&To[(size_t)iA*NTOK + j]) = vA;
      *reinterpret_cast<float2*>(&To[(size_t)iB*NTOK + j]) = vB;
    }
  }
}

// ============== Stage 4: LN(tri) @ Wo + bo, * gate (tf32 mma) ==============
#define LDT 129
#define FINAL_SMEM ((128*LDT + XS_WORDS + W_WORDS)*4)
__global__ __launch_bounds__(512) void final_kernel(const float* __restrict__ cg,
                                                    const float* __restrict__ cb,
                                                    const float* __restrict__ Wo,
                                                    const float* __restrict__ bo,
                                                    float* __restrict__ out){
  extern __shared__ uint32_t sm[];
  float*    T  = reinterpret_cast<float*>(sm);
  uint32_t* xs = sm + 128*LDT;
  uint32_t* w  = xs + XS_WORDS;
  __shared__ float p1[4][128], p2[4][128], mu_s[128], rs_s[128];
  int tid  = threadIdx.x;
  int row0 = blockIdx.x * 128;

  #pragma unroll
  for (int it=0; it<8; ++it){
    int slot = tid + it*512;
    int cch = slot >> 5;
    int v4  = slot & 31;
    float4 v = *reinterpret_cast<const float4*>(&g_tri[(size_t)cch*NROWS + row0 + v4*4]);
    T[cch*LDT + v4*4 + 0] = v.x;
    T[cch*LDT + v4*4 + 1] = v.y;
    T[cch*LDT + v4*4 + 2] = v.z;
    T[cch*LDT + v4*4 + 3] = v.w;
    v = *reinterpret_cast<const float4*>(&Wo[cch*CDIM + v4*4]);
    uint4 t; t.x=tf32_rna(v.x); t.y=tf32_rna(v.y); t.z=tf32_rna(v.z); t.w=tf32_rna(v.w);
    *reinterpret_cast<uint4*>(&w[cch*LDW + v4*4]) = t;
  }
  __syncthreads();

  {
    int ij = tid & 127, pp = tid >> 7;
    float s=0.f, s2=0.f;
    #pragma unroll
    for (int k=0;k<32;k++){
      float v = T[(pp*32+k)*LDT + ij];
      s += v; s2 += v*v;
    }
    p1[pp][ij] = s; p2[pp][ij] = s2;
  }
  __syncthreads();
  if (tid < 128){
    float s  = p1[0][tid]+p1[1][tid]+p1[2][tid]+p1[3][tid];
    float s2 = p2[0][tid]+p2[1][tid]+p2[2][tid]+p2[3][tid];
    float mu = s*(1.f/128.f);
    mu_s[tid] = mu;
    rs_s[tid] = rsqrtf(s2*(1.f/128.f) - mu*mu + EPSV);
  }
  __syncthreads();

  #pragma unroll
  for (int it=0; it<8; ++it){
    int slot = tid + it*512;
    int r  = slot & 127;
    int cq = slot >> 7;
    float mu = mu_s[r], rs = rs_s[r];
    uint4 t;
    {
      int c0 = cq*4;
      float v0 = (T[(c0+0)*LDT + r]-mu)*rs*cg[c0+0] + cb[c0+0];
      float v1 = (T[(c0+1)*LDT + r]-mu)*rs*cg[c0+1] + cb[c0+1];
      float v2 = (T[(c0+2)*LDT + r]-mu)*rs*cg[c0+2] + cb[c0+2];
      float v3 = (T[(c0+3)*LDT + r]-mu)*rs*cg[c0+3] + cb[c0+3];
      t.x=tf32_rna(v0); t.y=tf32_rna(v1); t.z=tf32_rna(v2); t.w=tf32_rna(v3);
    }
    *reinterpret_cast<uint4*>(&xs[r*LDX + cq*4]) = t;
  }
  __syncthreads();

  int lane = tid&31, wid = tid>>5;
  int wm = wid>>2, wn = wid&3;
  int gid = lane>>2, tig = lane&3;

  float acc[2][4][4], accd[2][4][4];
  #pragma unroll
  for (int t=0;t<2;t++)
    #pragma unroll
    for (int u=0;u<4;u++)
      #pragma unroll
      for (int r=0;r<4;r++) acc[t][u][r]=0.f;

  gemm_pair(xs, w, w, wm, wn, gid, tig, acc, accd, false);

  #pragma unroll
  for (int t=0;t<2;t++){
    int rowA = row0 + wm*32 + t*16 + gid;
    int rowB = rowA + 8;
    #pragma unroll
    for (int u=0;u<4;u++){
      int colb = wn*32 + u*8 + 2*tig;
      float bo0 = bo[colb], bo1 = bo[colb+1];
      float2 gA = *reinterpret_cast<const float2*>(&g_gate[(size_t)rowA*CDIM + colb]);
      float2 gB = *reinterpret_cast<const float2*>(&g_gate[(size_t)rowB*CDIM + colb]);
      float2 oA, oB;
      oA.x = (acc[t][u][0]+bo0)*gA.x;
      oA.y = (acc[t][u][1]+bo1)*gA.y;
      oB.x = (acc[t][u][2]+bo0)*gB.x;
      oB.y = (acc[t][u][3]+bo1)*gB.y;
      *reinterpret_cast<float2*>(&out[(size_t)rowA*CDIM + colb]) = oA;
      *reinterpret_cast<float2*>(&out[(size_t)rowB*CDIM + colb]) = oB;
    }
  }
}

extern "C" void kernel_launch(void* const* d_in, const int* in_sizes, int n_in,
                              void* d_out, int out_size) {
  const float* act  = (const float*)d_in[0];
  const float* mask = (const float*)d_in[1];
  const float* ln_g = (const float*)d_in[2];
  const float* ln_b = (const float*)d_in[3];
  const float* Wl   = (const float*)d_in[4];
  const float* bl   = (const float*)d_in[5];
  const float* Wr   = (const float*)d_in[6];
  const float* br   = (const float*)d_in[7];
  const float* Wgl  = (const float*)d_in[8];
  const float* bgl  = (const float*)d_in[9];
  const float* Wgr  = (const float*)d_in[10];
  const float* bgr  = (const float*)d_in[11];
  const float* cg   = (const float*)d_in[12];
  const float* cb   = (const float*)d_in[13];
  const float* Wo   = (const float*)d_in[14];
  const float* bo   = (const float*)d_in[15];
  const float* Wg   = (const float*)d_in[16];
  const float* bg   = (const float*)d_in[17];
  float* out = (float*)d_out;

  __nv_bfloat16 *dLh=nullptr, *dLl=nullptr, *dRh=nullptr, *dRl=nullptr;
  float *dGate=nullptr;
  cudaGetSymbolAddress((void**)&dLh, g_Lhi);
  cudaGetSymbolAddress((void**)&dLl, g_Llo);
  cudaGetSymbolAddress((void**)&dRh, g_Rhi);
  cudaGetSymbolAddress((void**)&dRl, g_Rlo);
  cudaGetSymbolAddress((void**)&dGate, g_gate);

  cudaFuncSetAttribute(proj_all_kernel, cudaFuncAttributeMaxDynamicSharedMemorySize, PROJALL_SMEM);
  cudaFuncSetAttribute(tri_kernel,      cudaFuncAttributeMaxDynamicSharedMemorySize, TRI_SMEM);
  cudaFuncSetAttribute(final_kernel,    cudaFuncAttributeMaxDynamicSharedMemorySize, FINAL_SMEM);

  proj_all_kernel<<<NROWS/128, 512, PROJALL_SMEM>>>(act, ln_g, ln_b, mask,
      Wl, bl, Wgl, bgl, Wr, br, Wgr, bgr, Wg, bg,
      dLh, dLl, dRh, dRl, dGate);
  tri_kernel<<<dim3(NTOK/64, NTOK/128, CDIM), 256, TRI_SMEM>>>();
  final_kernel<<<NROWS/128, 512, FINAL_SMEM>>>(cg, cb, Wo, bo, out);
}

// round 8
// speedup vs baseline: 3.9924x; 1.0491x over previous
#include <cuda_runtime.h>
#include <cuda_bf16.h>
#include <cstdint>
#include <math.h>

#define NTOK 384
#define CDIM 128
#define NROWS (NTOK*NTOK)   /* 147456 */
#define EPSV 1e-5f

// Scratch (no cudaMalloc allowed)
__device__ float g_gate[(size_t)NROWS*CDIM];
__device__ float g_tri [(size_t)NROWS*CDIM];           // [c][i*384+j]
__device__ __nv_bfloat16 g_Lhi[(size_t)CDIM*NROWS];    // [c][i*384+k]
__device__ __nv_bfloat16 g_Llo[(size_t)CDIM*NROWS];
__device__ __nv_bfloat16 g_Rhi[(size_t)CDIM*NROWS];    // [c][j*384+k]
__device__ __nv_bfloat16 g_Rlo[(size_t)CDIM*NROWS];

__device__ __forceinline__ float sigmoidf_(float z){ return 1.f/(1.f+expf(-z)); }

__device__ __forceinline__ uint32_t tf32_rna(float f){
  uint32_t r; asm("cvt.rna.tf32.f32 %0, %1;" : "=r"(r) : "f"(f)); return r;
}
__device__ __forceinline__ uint32_t prmt_(uint32_t a, uint32_t b, uint32_t s){
  uint32_t d; asm("prmt.b32 %0,%1,%2,%3;" : "=r"(d) : "r"(a), "r"(b), "r"(s)); return d;
}
__device__ __forceinline__ uint32_t pack_hilo(float v){
  __nv_bfloat16 h = __float2bfloat16(v);
  float rem = v - __bfloat162float(h);
  __nv_bfloat16 l = __float2bfloat16(rem);
  uint16_t hb = *reinterpret_cast<uint16_t*>(&h);
  uint16_t lb = *reinterpret_cast<uint16_t*>(&l);
  return (uint32_t)hb | ((uint32_t)lb << 16);
}
__device__ __forceinline__ uint32_t smem_u32(const void* p){
  uint32_t a;
  asm("{ .reg .u64 t; cvta.to.shared.u64 t, %1; cvt.u32.u64 %0, t; }" : "=r"(a) : "l"(p));
  return a;
}
__device__ __forceinline__ void cp16(uint32_t dst_smem, const void* src){
  asm volatile("cp.async.ca.shared.global [%0], [%1], 16;" :: "r"(dst_smem), "l"(src));
}
__device__ __forceinline__ void cp_commit_wait(){
  asm volatile("cp.async.commit_group;");
  asm volatile("cp.async.wait_group 0;");
}

// m16n8k8 tf32 mma (sm_80 base ISA)
__device__ __forceinline__ void mma_tf32(float& d0, float& d1, float& d2, float& d3,
                                         uint32_t a0, uint32_t a1, uint32_t a2, uint32_t a3,
                                         uint32_t b0, uint32_t b1){
  asm volatile(
    "mma.sync.aligned.m16n8k8.row.col.f32.tf32.tf32.f32 "
    "{%0,%1,%2,%3}, {%4,%5,%6,%7}, {%8,%9}, {%0,%1,%2,%3};"
    : "+f"(d0), "+f"(d1), "+f"(d2), "+f"(d3)
    : "r"(a0), "r"(a1), "r"(a2), "r"(a3), "r"(b0), "r"(b1));
}

// m16n8k16 bf16 mma (sm_80 base ISA)
__device__ __forceinline__ void mma_bf16(float* d, const uint32_t* a, uint32_t b0, uint32_t b1){
  asm volatile(
    "mma.sync.aligned.m16n8k16.row.col.f32.bf16.bf16.f32 "
    "{%0,%1,%2,%3}, {%4,%5,%6,%7}, {%8,%9}, {%0,%1,%2,%3};"
    : "+f"(d[0]), "+f"(d[1]), "+f"(d[2]), "+f"(d[3])
    : "r"(a[0]), "r"(a[1]), "r"(a[2]), "r"(a[3]), "r"(b0), "r"(b1));
}

// ================= fused LN + 5 projections =================
#define LDX 132
#define LDW 136
#define LDE 132
#define XS_WORDS (128*LDX)
#define W_WORDS  (128*LDW)
#define EBUF_WORDS (32*LDE)
#define PROJALL_SMEM ((XS_WORDS + 2*W_WORDS + EBUF_WORDS)*4)

// GEMM-pair mainloop: acc1 += xs@w1, (dual) acc2 += xs@w2
__device__ __forceinline__ void gemm_pair(const uint32_t* __restrict__ xs,
                                          const uint32_t* __restrict__ w1,
                                          const uint32_t* __restrict__ w2,
                                          int wm, int wn, int gid, int tig,
                                          float acc1[2][4][4], float acc2[2][4][4],
                                          bool dual){
  const uint32_t* xa  = xs + (wm*32 + gid)*LDX + tig;
  const uint32_t* wb1 = w1 + tig*LDW + wn*32 + gid;
  const uint32_t* wb2 = w2 + tig*LDW + wn*32 + gid;
  #pragma unroll
  for (int kc=0; kc<16; kc++){
    uint32_t a[2][4];
    #pragma unroll
    for (int t=0;t<2;t++){
      const uint32_t* p = xa + t*16*LDX + kc*8;
      a[t][0] = p[0];
      a[t][1] = p[8*LDX];
      a[t][2] = p[4];
      a[t][3] = p[8*LDX + 4];
    }
    #pragma unroll
    for (int u=0;u<4;u++){
      const uint32_t* q1 = wb1 + kc*8*LDW + u*8;
      uint32_t b10 = q1[0], b11 = q1[4*LDW];
      #pragma unroll
      for (int t=0;t<2;t++)
        mma_tf32(acc1[t][u][0],acc1[t][u][1],acc1[t][u][2],acc1[t][u][3],
                 a[t][0],a[t][1],a[t][2],a[t][3], b10,b11);
      if (dual){
        const uint32_t* q2 = wb2 + kc*8*LDW + u*8;
        uint32_t b20 = q2[0], b21 = q2[4*LDW];
        #pragma unroll
        for (int t=0;t<2;t++)
          mma_tf32(acc2[t][u][0],acc2[t][u][1],acc2[t][u][2],acc2[t][u][3],
                   a[t][0],a[t][1],a[t][2],a[t][3], b20,b21);
      }
    }
  }
}

// LDG one 128x128 W into registers (raw fp32 bits)
__device__ __forceinline__ void ldgW(const float* __restrict__ W, int tid, uint4 w[8]){
  #pragma unroll
  for (int it=0; it<8; ++it){
    int slot = tid + it*512;
    int r  = slot >> 5;
    int kv = slot & 31;
    w[it] = *reinterpret_cast<const uint4*>(&W[r*CDIM + kv*4]);
  }
}
// cvt tf32 + STS into a W smem buffer
__device__ __forceinline__ void stsW(const uint4 w[8], int tid, uint32_t* __restrict__ dst){
  #pragma unroll
  for (int it=0; it<8; ++it){
    int slot = tid + it*512;
    int r  = slot >> 5;
    int kv = slot & 31;
    float4 v = *reinterpret_cast<const float4*>(&w[it]);
    uint4 t; t.x=tf32_rna(v.x); t.y=tf32_rna(v.y); t.z=tf32_rna(v.z); t.w=tf32_rna(v.w);
    *reinterpret_cast<uint4*>(&dst[r*LDW + kv*4]) = t;
  }
}

// bias+sigmoid+mask -> (hi,lo) packed words
__device__ __forceinline__ void compute_pk(const float acc1[2][4][4], const float acc2[2][4][4],
    const float* __restrict__ mask, const float* __restrict__ bb1, const float* __restrict__ bb2,
    int row0, int wm, int wn, int gid, int tig, uint32_t pk[32]){
  #pragma unroll
  for (int t=0;t<2;t++){
    int rA = wm*32 + t*16 + gid;
    int rB = rA + 8;
    float mvA = mask[row0 + rA], mvB = mask[row0 + rB];
    #pragma unroll
    for (int u=0;u<4;u++){
      int colb = wn*32 + u*8 + 2*tig;
      float2 b1v = *reinterpret_cast<const float2*>(&bb1[colb]);
      float2 b2v = *reinterpret_cast<const float2*>(&bb2[colb]);
      float v0 = mvA*(acc1[t][u][0]+b1v.x)*sigmoidf_(acc2[t][u][0]+b2v.x);
      float v1 = mvA*(acc1[t][u][1]+b1v.y)*sigmoidf_(acc2[t][u][1]+b2v.y);
      float v2 = mvB*(acc1[t][u][2]+b1v.x)*sigmoidf_(acc2[t][u][2]+b2v.x);
      float v3 = mvB*(acc1[t][u][3]+b1v.y)*sigmoidf_(acc2[t][u][3]+b2v.y);
      pk[t*16+u*4+0] = pack_hilo(v0);
      pk[t*16+u*4+1] = pack_hilo(v1);
      pk[t*16+u*4+2] = pack_hilo(v2);
      pk[t*16+u*4+3] = pack_hilo(v3);
    }
  }
}

// 4-pass packed epilogue store
__device__ __forceinline__ void epi_store(const uint32_t pk[32], uint32_t* __restrict__ ebuf,
    __nv_bfloat16* __restrict__ ghi, __nv_bfloat16* __restrict__ glo,
    int row0, int tid, int wm, int wn, int gid, int tig){
  #pragma unroll
  for (int p=0;p<4;p++){
    if (wn == p){
      #pragma unroll
      for (int t=0;t<2;t++){
        int rA = wm*32 + t*16 + gid;
        int rB = rA + 8;
        #pragma unroll
        for (int u=0;u<4;u++){
          int cl = u*8 + 2*tig;
          ebuf[ cl   *LDE + rA] = pk[t*16+u*4+0];
          ebuf[(cl+1)*LDE + rA] = pk[t*16+u*4+1];
          ebuf[ cl   *LDE + rB] = pk[t*16+u*4+2];
          ebuf[(cl+1)*LDE + rB] = pk[t*16+u*4+3];
        }
      }
    }
    __syncthreads();
    {
      int cl = tid >> 4;
      int rb = tid & 15;
      #pragma unroll
      for (int h=0; h<2; h++){
        int rq = rb + 16*h;
        uint4 w = *reinterpret_cast<const uint4*>(&ebuf[cl*LDE + rq*4]);
        uint32_t hi01 = prmt_(w.x, w.y, 0x5410u);
        uint32_t hi23 = prmt_(w.z, w.w, 0x5410u);
        uint32_t lo01 = prmt_(w.x, w.y, 0x7632u);
        uint32_t lo23 = prmt_(w.z, w.w, 0x7632u);
        size_t base = (size_t)(p*32 + cl)*NROWS + row0 + rq*4;
        *reinterpret_cast<uint2*>(&ghi[base]) = make_uint2(hi01, hi23);
        *reinterpret_cast<uint2*>(&glo[base]) = make_uint2(lo01, lo23);
      }
    }
    __syncthreads();
  }
}

__global__ __launch_bounds__(512) void proj_all_kernel(
    const float* __restrict__ act, const float* __restrict__ lng, const float* __restrict__ lnb,
    const float* __restrict__ mask,
    const float* __restrict__ Wl,  const float* __restrict__ bl,
    const float* __restrict__ Wgl, const float* __restrict__ bgl,
    const float* __restrict__ Wr,  const float* __restrict__ br,
    const float* __restrict__ Wgr, const float* __restrict__ bgr,
    const float* __restrict__ Wg,  const float* __restrict__ bg,
    __nv_bfloat16* __restrict__ gLh, __nv_bfloat16* __restrict__ gLl,
    __nv_bfloat16* __restrict__ gRh, __nv_bfloat16* __restrict__ gRl,
    float* __restrict__ gate){
  extern __shared__ uint32_t sm[];
  uint32_t* xs   = sm;
  uint32_t* w1   = sm + XS_WORDS;
  uint32_t* w2   = w1 + W_WORDS;
  uint32_t* ebuf = w2 + W_WORDS;
  int tid  = threadIdx.x;
  int row0 = blockIdx.x * 128;
  int kv   = tid & 31;

  {
    uint4 va[8];
    #pragma unroll
    for (int it=0; it<8; ++it){
      int r = (tid>>5) + it*16;
      va[it] = *reinterpret_cast<const uint4*>(&act[(size_t)(row0+r)*CDIM + kv*4]);
    }
    uint4 wA[8], wB[8];
    ldgW(Wl,  tid, wA);
    ldgW(Wgl, tid, wB);
    float4 g4 = *reinterpret_cast<const float4*>(&lng[kv*4]);
    float4 b4 = *reinterpret_cast<const float4*>(&lnb[kv*4]);
    #pragma unroll
    for (int it=0; it<8; ++it){
      int r = (tid>>5) + it*16;
      float4 v = *reinterpret_cast<const float4*>(&va[it]);
      float s  = v.x + v.y + v.z + v.w;
      float s2 = v.x*v.x + v.y*v.y + v.z*v.z + v.w*v.w;
      #pragma unroll
      for (int off=16; off>0; off>>=1){
        s  += __shfl_xor_sync(0xffffffffu, s,  off);
        s2 += __shfl_xor_sync(0xffffffffu, s2, off);
      }
      float mu = s * (1.f/128.f);
      float rs = rsqrtf(s2*(1.f/128.f) - mu*mu + EPSV);
      uint4 t;
      t.x = tf32_rna((v.x-mu)*rs*g4.x + b4.x);
      t.y = tf32_rna((v.y-mu)*rs*g4.y + b4.y);
      t.z = tf32_rna((v.z-mu)*rs*g4.z + b4.z);
      t.w = tf32_rna((v.w-mu)*rs*g4.w + b4.w);
      *reinterpret_cast<uint4*>(&xs[r*LDX + kv*4]) = t;
    }
    stsW(wA, tid, w1);
    stsW(wB, tid, w2);
  }
  __syncthreads();

  int lane = tid&31, wid = tid>>5;
  int wm = wid>>2, wn = wid&3;
  int gid = lane>>2, tig = lane&3;

  float acc1[2][4][4], acc2[2][4][4];
  uint32_t pk[32];

  // ---- GEMM 1: left (dual) ----
  #pragma unroll
  for (int t=0;t<2;t++)
    #pragma unroll
    for (int u=0;u<4;u++)
      #pragma unroll
      for (int r=0;r<4;r++){ acc1[t][u][r]=0.f; acc2[t][u][r]=0.f; }
  gemm_pair(xs, w1, w2, wm, wn, gid, tig, acc1, acc2, true);
  compute_pk(acc1, acc2, mask, bl, bgl, row0, wm, wn, gid, tig, pk);
  {
    uint4 wA[8], wB[8];
    ldgW(Wr,  tid, wA);
    ldgW(Wgr, tid, wB);
    epi_store(pk, ebuf, gLh, gLl, row0, tid, wm, wn, gid, tig);
    stsW(wA, tid, w1);
    stsW(wB, tid, w2);
  }
  __syncthreads();

  // ---- GEMM 2: right (dual) ----
  #pragma unroll
  for (int t=0;t<2;t++)
    #pragma unroll
    for (int u=0;u<4;u++)
      #pragma unroll
      for (int r=0;r<4;r++){ acc1[t][u][r]=0.f; acc2[t][u][r]=0.f; }
  gemm_pair(xs, w1, w2, wm, wn, gid, tig, acc1, acc2, true);
  compute_pk(acc1, acc2, mask, br, bgr, row0, wm, wn, gid, tig, pk);
  {
    uint4 wA[8];
    ldgW(Wg, tid, wA);
    epi_store(pk, ebuf, gRh, gRl, row0, tid, wm, wn, gid, tig);
    stsW(wA, tid, w1);
  }
  __syncthreads();

  // ---- GEMM 3: gate (single) ----
  #pragma unroll
  for (int t=0;t<2;t++)
    #pragma unroll
    for (int u=0;u<4;u++)
      #pragma unroll
      for (int r=0;r<4;r++) acc1[t][u][r]=0.f;
  gemm_pair(xs, w1, w1, wm, wn, gid, tig, acc1, acc2, false);
  #pragma unroll
  for (int t=0;t<2;t++){
    int rowA = row0 + wm*32 + t*16 + gid;
    int rowB = rowA + 8;
    #pragma unroll
    for (int u=0;u<4;u++){
      int colb = wn*32 + u*8 + 2*tig;
      float b0 = bg[colb], b1 = bg[colb+1];
      float2 oA, oB;
      oA.x = sigmoidf_(acc1[t][u][0]+b0);
      oA.y = sigmoidf_(acc1[t][u][1]+b1);
      oB.x = sigmoidf_(acc1[t][u][2]+b0);
      oB.y = sigmoidf_(acc1[t][u][3]+b1);
      *reinterpret_cast<float2*>(&gate[(size_t)rowA*CDIM + colb]) = oA;
      *reinterpret_cast<float2*>(&gate[(size_t)rowB*CDIM + colb]) = oB;
    }
  }
}

// ============== Stage 3: per-channel GEMM via bf16-split mma ==============
// cp.async staging + forced 2 CTAs/SM (regs<=128, smem 55KB -> 2 fit).
#define TRI_LDS 72
#define TRI_SMEM ((64*TRI_LDS*2 + 128*TRI_LDS*2)*2)
__global__ __launch_bounds__(256, 2) void tri_kernel(){
  extern __shared__ __nv_bfloat16 smb[];
  __nv_bfloat16* Lhi = smb;
  __nv_bfloat16* Llo = smb + 64*TRI_LDS;
  __nv_bfloat16* Rhi = smb + 2*64*TRI_LDS;
  __nv_bfloat16* Rlo = Rhi + 128*TRI_LDS;
  uint32_t sLhi = smem_u32(Lhi);
  uint32_t sLlo = smem_u32(Llo);
  uint32_t sRhi = smem_u32(Rhi);
  uint32_t sRlo = smem_u32(Rlo);
  int tid = threadIdx.x;
  int c  = blockIdx.z;
  int i0 = blockIdx.x * 64;
  int j0 = blockIdx.y * 128;
  const __nv_bfloat16* gLh = g_Lhi + (size_t)c*NROWS;
  const __nv_bfloat16* gLl = g_Llo + (size_t)c*NROWS;
  const __nv_bfloat16* gRh = g_Rhi + (size_t)c*NROWS;
  const __nv_bfloat16* gRl = g_Rlo + (size_t)c*NROWS;

  int lane = tid&31, wid = tid>>5;
  int wm = wid>>2, wn = wid&3;
  int gid = lane>>2, tig = lane&3;

  // per-thread staging coordinates (constant across chunks)
  int sr = tid>>3, sseg = tid&7;        // L: rows 0..31 (+32 second it), R: 0..31 (+32,64,96)

  float acc[2][4][4];
  #pragma unroll
  for (int t=0;t<2;t++)
    #pragma unroll
    for (int u=0;u<4;u++)
      #pragma unroll
      for (int r=0;r<4;r++) acc[t][u][r]=0.f;

  for (int kc=0; kc<NTOK; kc+=64){
    __syncthreads();
    #pragma unroll
    for (int it=0; it<2; it++){
      int r = sr + it*32;
      size_t go = (size_t)(i0+r)*NTOK + kc + sseg*8;
      uint32_t so = (uint32_t)(r*TRI_LDS + sseg*8)*2;
      cp16(sLhi + so, &gLh[go]);
      cp16(sLlo + so, &gLl[go]);
    }
    #pragma unroll
    for (int it=0; it<4; it++){
      int r = sr + it*32;
      size_t go = (size_t)(j0+r)*NTOK + kc + sseg*8;
      uint32_t so = (uint32_t)(r*TRI_LDS + sseg*8)*2;
      cp16(sRhi + so, &gRh[go]);
      cp16(sRlo + so, &gRl[go]);
    }
    cp_commit_wait();
    __syncthreads();

    #pragma unroll
    for (int ks=0; ks<4; ks++){
      int ko = ks*16;
      uint32_t ah[2][4], al[2][4];
      #pragma unroll
      for (int t=0;t<2;t++){
        int row = wm*32 + t*16 + gid;
        int base = row*TRI_LDS + ko + 2*tig;
        ah[t][0] = *reinterpret_cast<const uint32_t*>(&Lhi[base]);
        ah[t][1] = *reinterpret_cast<const uint32_t*>(&Lhi[base + 8*TRI_LDS]);
        ah[t][2] = *reinterpret_cast<const uint32_t*>(&Lhi[base + 8]);
        ah[t][3] = *reinterpret_cast<const uint32_t*>(&Lhi[base + 8*TRI_LDS + 8]);
        al[t][0] = *reinterpret_cast<const uint32_t*>(&Llo[base]);
        al[t][1] = *reinterpret_cast<const uint32_t*>(&Llo[base + 8*TRI_LDS]);
        al[t][2] = *reinterpret_cast<const uint32_t*>(&Llo[base + 8]);
        al[t][3] = *reinterpret_cast<const uint32_t*>(&Llo[base + 8*TRI_LDS + 8]);
      }
      #pragma unroll
      for (int u=0;u<4;u++){
        int jrow = wn*32 + u*8 + gid;
        int bb = jrow*TRI_LDS + ko + 2*tig;
        uint32_t bh0 = *reinterpret_cast<const uint32_t*>(&Rhi[bb]);
        uint32_t bh1 = *reinterpret_cast<const uint32_t*>(&Rhi[bb + 8]);
        uint32_t bl0 = *reinterpret_cast<const uint32_t*>(&Rlo[bb]);
        uint32_t bl1 = *reinterpret_cast<const uint32_t*>(&Rlo[bb + 8]);
        #pragma unroll
        for (int t=0;t<2;t++){
          mma_bf16(acc[t][u], ah[t], bh0, bh1);
          mma_bf16(acc[t][u], ah[t], bl0, bl1);
          mma_bf16(acc[t][u], al[t], bh0, bh1);
        }
      }
    }
  }

  float* To = g_tri + (size_t)c*NROWS;
  #pragma unroll
  for (int t=0;t<2;t++){
    int iA = i0 + wm*32 + t*16 + gid;
    int iB = iA + 8;
    #pragma unroll
    for (int u=0;u<4;u++){
      int j = j0 + wn*32 + u*8 + 2*tig;
      float2 vA = {acc[t][u][0], acc[t][u][1]};
      float2 vB = {acc[t][u][2], acc[t][u][3]};
      *reinterpret_cast<float2*>(&To[(size_t)iA*NTOK + j]) = vA;
      *reinterpret_cast<float2*>(&To[(size_t)iB*NTOK + j]) = vB;
    }
  }
}

// ============== Stage 4: LN(tri) @ Wo + bo, * gate (tf32 mma) ==============
#define LDT 129
#define FINAL_SMEM ((128*LDT + XS_WORDS + W_WORDS)*4)
__global__ __launch_bounds__(512) void final_kernel(const float* __restrict__ cg,
                                                    const float* __restrict__ cb,
                                                    const float* __restrict__ Wo,
                                                    const float* __restrict__ bo,
                                                    float* __restrict__ out){
  extern __shared__ uint32_t sm[];
  float*    T  = reinterpret_cast<float*>(sm);
  uint32_t* xs = sm + 128*LDT;
  uint32_t* w  = xs + XS_WORDS;
  __shared__ float p1[4][128], p2[4][128], mu_s[128], rs_s[128];
  int tid  = threadIdx.x;
  int row0 = blockIdx.x * 128;

  #pragma unroll
  for (int it=0; it<8; ++it){
    int slot = tid + it*512;
    int cch = slot >> 5;
    int v4  = slot & 31;
    float4 v = *reinterpret_cast<const float4*>(&g_tri[(size_t)cch*NROWS + row0 + v4*4]);
    T[cch*LDT + v4*4 + 0] = v.x;
    T[cch*LDT + v4*4 + 1] = v.y;
    T[cch*LDT + v4*4 + 2] = v.z;
    T[cch*LDT + v4*4 + 3] = v.w;
    v = *reinterpret_cast<const float4*>(&Wo[cch*CDIM + v4*4]);
    uint4 t; t.x=tf32_rna(v.x); t.y=tf32_rna(v.y); t.z=tf32_rna(v.z); t.w=tf32_rna(v.w);
    *reinterpret_cast<uint4*>(&w[cch*LDW + v4*4]) = t;
  }
  __syncthreads();

  {
    int ij = tid & 127, pp = tid >> 7;
    float s=0.f, s2=0.f;
    #pragma unroll
    for (int k=0;k<32;k++){
      float v = T[(pp*32+k)*LDT + ij];
      s += v; s2 += v*v;
    }
    p1[pp][ij] = s; p2[pp][ij] = s2;
  }
  __syncthreads();
  if (tid < 128){
    float s  = p1[0][tid]+p1[1][tid]+p1[2][tid]+p1[3][tid];
    float s2 = p2[0][tid]+p2[1][tid]+p2[2][tid]+p2[3][tid];
    float mu = s*(1.f/128.f);
    mu_s[tid] = mu;
    rs_s[tid] = rsqrtf(s2*(1.f/128.f) - mu*mu + EPSV);
  }
  __syncthreads();

  #pragma unroll
  for (int it=0; it<8; ++it){
    int slot = tid + it*512;
    int r  = slot & 127;
    int cq = slot >> 7;
    float mu = mu_s[r], rs = rs_s[r];
    uint4 t;
    {
      int c0 = cq*4;
      float v0 = (T[(c0+0)*LDT + r]-mu)*rs*cg[c0+0] + cb[c0+0];
      float v1 = (T[(c0+1)*LDT + r]-mu)*rs*cg[c0+1] + cb[c0+1];
      float v2 = (T[(c0+2)*LDT + r]-mu)*rs*cg[c0+2] + cb[c0+2];
      float v3 = (T[(c0+3)*LDT + r]-mu)*rs*cg[c0+3] + cb[c0+3];
      t.x=tf32_rna(v0); t.y=tf32_rna(v1); t.z=tf32_rna(v2); t.w=tf32_rna(v3);
    }
    *reinterpret_cast<uint4*>(&xs[r*LDX + cq*4]) = t;
  }
  __syncthreads();

  int lane = tid&31, wid = tid>>5;
  int wm = wid>>2, wn = wid&3;
  int gid = lane>>2, tig = lane&3;

  float acc[2][4][4], accd[2][4][4];
  #pragma unroll
  for (int t=0;t<2;t++)
    #pragma unroll
    for (int u=0;u<4;u++)
      #pragma unroll
      for (int r=0;r<4;r++) acc[t][u][r]=0.f;

  gemm_pair(xs, w, w, wm, wn, gid, tig, acc, accd, false);

  #pragma unroll
  for (int t=0;t<2;t++){
    int rowA = row0 + wm*32 + t*16 + gid;
    int rowB = rowA + 8;
    #pragma unroll
    for (int u=0;u<4;u++){
      int colb = wn*32 + u*8 + 2*tig;
      float bo0 = bo[colb], bo1 = bo[colb+1];
      float2 gA = *reinterpret_cast<const float2*>(&g_gate[(size_t)rowA*CDIM + colb]);
      float2 gB = *reinterpret_cast<const float2*>(&g_gate[(size_t)rowB*CDIM + colb]);
      float2 oA, oB;
      oA.x = (acc[t][u][0]+bo0)*gA.x;
      oA.y = (acc[t][u][1]+bo1)*gA.y;
      oB.x = (acc[t][u][2]+bo0)*gB.x;
      oB.y = (acc[t][u][3]+bo1)*gB.y;
      *reinterpret_cast<float2*>(&out[(size_t)rowA*CDIM + colb]) = oA;
      *reinterpret_cast<float2*>(&out[(size_t)rowB*CDIM + colb]) = oB;
    }
  }
}

extern "C" void kernel_launch(void* const* d_in, const int* in_sizes, int n_in,
                              void* d_out, int out_size) {
  const float* act  = (const float*)d_in[0];
  const float* mask = (const float*)d_in[1];
  const float* ln_g = (const float*)d_in[2];
  const float* ln_b = (const float*)d_in[3];
  const float* Wl   = (const float*)d_in[4];
  const float* bl   = (const float*)d_in[5];
  const float* Wr   = (const float*)d_in[6];
  const float* br   = (const float*)d_in[7];
  const float* Wgl  = (const float*)d_in[8];
  const float* bgl  = (const float*)d_in[9];
  const float* Wgr  = (const float*)d_in[10];
  const float* bgr  = (const float*)d_in[11];
  const float* cg   = (const float*)d_in[12];
  const float* cb   = (const float*)d_in[13];
  const float* Wo   = (const float*)d_in[14];
  const float* bo   = (const float*)d_in[15];
  const float* Wg   = (const float*)d_in[16];
  const float* bg   = (const float*)d_in[17];
  float* out = (float*)d_out;

  __nv_bfloat16 *dLh=nullptr, *dLl=nullptr, *dRh=nullptr, *dRl=nullptr;
  float *dGate=nullptr;
  cudaGetSymbolAddress((void**)&dLh, g_Lhi);
  cudaGetSymbolAddress((void**)&dLl, g_Llo);
  cudaGetSymbolAddress((void**)&dRh, g_Rhi);
  cudaGetSymbolAddress((void**)&dRl, g_Rlo);
  cudaGetSymbolAddress((void**)&dGate, g_gate);

  cudaFuncSetAttribute(proj_all_kernel, cudaFuncAttributeMaxDynamicSharedMemorySize, PROJALL_SMEM);
  cudaFuncSetAttribute(tri_kernel,      cudaFuncAttributeMaxDynamicSharedMemorySize, TRI_SMEM);
  cudaFuncSetAttribute(final_kernel,    cudaFuncAttributeMaxDynamicSharedMemorySize, FINAL_SMEM);

  proj_all_kernel<<<NROWS/128, 512, PROJALL_SMEM>>>(act, ln_g, ln_b, mask,
      Wl, bl, Wgl, bgl, Wr, br, Wgr, bgr, Wg, bg,
      dLh, dLl, dRh, dRl, dGate);
  tri_kernel<<<dim3(NTOK/64, NTOK/128, CDIM), 256, TRI_SMEM>>>();
  final_kernel<<<NROWS/128, 512, FINAL_SMEM>>>(cg, cb, Wo, bo, out);
}

// round 9
// speedup vs baseline: 4.3197x; 1.0820x over previous
#include <cuda_runtime.h>
#include <cuda_bf16.h>
#include <cstdint>
#include <math.h>

#define NTOK 384
#define CDIM 128
#define NROWS (NTOK*NTOK)   /* 147456 */
#define EPSV 1e-5f

// Scratch (no cudaMalloc allowed)
__device__ float g_gate[(size_t)NROWS*CDIM];
__device__ float g_tri [(size_t)NROWS*CDIM];           // [c][i*384+j]
__device__ __nv_bfloat16 g_Lhi[(size_t)CDIM*NROWS];    // [c][i*384+k]
__device__ __nv_bfloat16 g_Llo[(size_t)CDIM*NROWS];
__device__ __nv_bfloat16 g_Rhi[(size_t)CDIM*NROWS];    // [c][j*384+k]
__device__ __nv_bfloat16 g_Rlo[(size_t)CDIM*NROWS];

// fast sigmoid: MUFU.EX2 + MUFU.RCP path (rel err ~2^-21, tolerance is 1e-3)
__device__ __forceinline__ float fsig(float z){
  return __fdividef(1.f, 1.f + __expf(-z));
}

__device__ __forceinline__ uint32_t tf32_rna(float f){
  uint32_t r; asm("cvt.rna.tf32.f32 %0, %1;" : "=r"(r) : "f"(f)); return r;
}
__device__ __forceinline__ uint32_t prmt_(uint32_t a, uint32_t b, uint32_t s){
  uint32_t d; asm("prmt.b32 %0,%1,%2,%3;" : "=r"(d) : "r"(a), "r"(b), "r"(s)); return d;
}
__device__ __forceinline__ uint32_t pack_hilo(float v){
  __nv_bfloat16 h = __float2bfloat16(v);
  float rem = v - __bfloat162float(h);
  __nv_bfloat16 l = __float2bfloat16(rem);
  uint16_t hb = *reinterpret_cast<uint16_t*>(&h);
  uint16_t lb = *reinterpret_cast<uint16_t*>(&l);
  return (uint32_t)hb | ((uint32_t)lb << 16);
}
__device__ __forceinline__ uint32_t smem_u32(const void* p){
  uint32_t a;
  asm("{ .reg .u64 t; cvta.to.shared.u64 t, %1; cvt.u32.u64 %0, t; }" : "=r"(a) : "l"(p));
  return a;
}
__device__ __forceinline__ void cp16(uint32_t dst_smem, const void* src){
  asm volatile("cp.async.ca.shared.global [%0], [%1], 16;" :: "r"(dst_smem), "l"(src));
}
__device__ __forceinline__ void cp_commit_wait(){
  asm volatile("cp.async.commit_group;");
  asm volatile("cp.async.wait_group 0;");
}

// m16n8k8 tf32 mma (sm_80 base ISA)
__device__ __forceinline__ void mma_tf32(float& d0, float& d1, float& d2, float& d3,
                                         uint32_t a0, uint32_t a1, uint32_t a2, uint32_t a3,
                                         uint32_t b0, uint32_t b1){
  asm volatile(
    "mma.sync.aligned.m16n8k8.row.col.f32.tf32.tf32.f32 "
    "{%0,%1,%2,%3}, {%4,%5,%6,%7}, {%8,%9}, {%0,%1,%2,%3};"
    : "+f"(d0), "+f"(d1), "+f"(d2), "+f"(d3)
    : "r"(a0), "r"(a1), "r"(a2), "r"(a3), "r"(b0), "r"(b1));
}

// m16n8k16 bf16 mma (sm_80 base ISA)
__device__ __forceinline__ void mma_bf16(float* d, const uint32_t* a, uint32_t b0, uint32_t b1){
  asm volatile(
    "mma.sync.aligned.m16n8k16.row.col.f32.bf16.bf16.f32 "
    "{%0,%1,%2,%3}, {%4,%5,%6,%7}, {%8,%9}, {%0,%1,%2,%3};"
    : "+f"(d[0]), "+f"(d[1]), "+f"(d[2]), "+f"(d[3])
    : "r"(a[0]), "r"(a[1]), "r"(a[2]), "r"(a[3]), "r"(b0), "r"(b1));
}

// ================= fused LN + 5 projections =================
#define LDX 132
#define LDW 136
#define LDE 132
#define XS_WORDS (128*LDX)
#define W_WORDS  (128*LDW)
#define PROJALL_SMEM ((XS_WORDS + 2*W_WORDS)*4)

// GEMM-pair mainloop: acc1 += xs@w1, (dual) acc2 += xs@w2
__device__ __forceinline__ void gemm_pair(const uint32_t* __restrict__ xs,
                                          const uint32_t* __restrict__ w1,
                                          const uint32_t* __restrict__ w2,
                                          int wm, int wn, int gid, int tig,
                                          float acc1[2][4][4], float acc2[2][4][4],
                                          bool dual){
  const uint32_t* xa  = xs + (wm*32 + gid)*LDX + tig;
  const uint32_t* wb1 = w1 + tig*LDW + wn*32 + gid;
  const uint32_t* wb2 = w2 + tig*LDW + wn*32 + gid;
  #pragma unroll
  for (int kc=0; kc<16; kc++){
    uint32_t a[2][4];
    #pragma unroll
    for (int t=0;t<2;t++){
      const uint32_t* p = xa + t*16*LDX + kc*8;
      a[t][0] = p[0];
      a[t][1] = p[8*LDX];
      a[t][2] = p[4];
      a[t][3] = p[8*LDX + 4];
    }
    #pragma unroll
    for (int u=0;u<4;u++){
      const uint32_t* q1 = wb1 + kc*8*LDW + u*8;
      uint32_t b10 = q1[0], b11 = q1[4*LDW];
      #pragma unroll
      for (int t=0;t<2;t++)
        mma_tf32(acc1[t][u][0],acc1[t][u][1],acc1[t][u][2],acc1[t][u][3],
                 a[t][0],a[t][1],a[t][2],a[t][3], b10,b11);
      if (dual){
        const uint32_t* q2 = wb2 + kc*8*LDW + u*8;
        uint32_t b20 = q2[0], b21 = q2[4*LDW];
        #pragma unroll
        for (int t=0;t<2;t++)
          mma_tf32(acc2[t][u][0],acc2[t][u][1],acc2[t][u][2],acc2[t][u][3],
                   a[t][0],a[t][1],a[t][2],a[t][3], b20,b21);
      }
    }
  }
}

// LDG one 128x128 W into registers (raw fp32 bits)
__device__ __forceinline__ void ldgW(const float* __restrict__ W, int tid, uint4 w[8]){
  #pragma unroll
  for (int it=0; it<8; ++it){
    int slot = tid + it*512;
    int r  = slot >> 5;
    int kv = slot & 31;
    w[it] = *reinterpret_cast<const uint4*>(&W[r*CDIM + kv*4]);
  }
}
// cvt tf32 + STS into a W smem buffer
__device__ __forceinline__ void stsW(const uint4 w[8], int tid, uint32_t* __restrict__ dst){
  #pragma unroll
  for (int it=0; it<8; ++it){
    int slot = tid + it*512;
    int r  = slot >> 5;
    int kv = slot & 31;
    float4 v = *reinterpret_cast<const float4*>(&w[it]);
    uint4 t; t.x=tf32_rna(v.x); t.y=tf32_rna(v.y); t.z=tf32_rna(v.z); t.w=tf32_rna(v.w);
    *reinterpret_cast<uint4*>(&dst[r*LDW + kv*4]) = t;
  }
}

// bias+sigmoid+mask -> (hi,lo) packed words
__device__ __forceinline__ void compute_pk(const float acc1[2][4][4], const float acc2[2][4][4],
    const float* __restrict__ mask, const float* __restrict__ bb1, const float* __restrict__ bb2,
    int row0, int wm, int wn, int gid, int tig, uint32_t pk[32]){
  #pragma unroll
  for (int t=0;t<2;t++){
    int rA = wm*32 + t*16 + gid;
    int rB = rA + 8;
    float mvA = mask[row0 + rA], mvB = mask[row0 + rB];
    #pragma unroll
    for (int u=0;u<4;u++){
      int colb = wn*32 + u*8 + 2*tig;
      float2 b1v = *reinterpret_cast<const float2*>(&bb1[colb]);
      float2 b2v = *reinterpret_cast<const float2*>(&bb2[colb]);
      float v0 = mvA*(acc1[t][u][0]+b1v.x)*fsig(acc2[t][u][0]+b2v.x);
      float v1 = mvA*(acc1[t][u][1]+b1v.y)*fsig(acc2[t][u][1]+b2v.y);
      float v2 = mvB*(acc1[t][u][2]+b1v.x)*fsig(acc2[t][u][2]+b2v.x);
      float v3 = mvB*(acc1[t][u][3]+b1v.y)*fsig(acc2[t][u][3]+b2v.y);
      pk[t*16+u*4+0] = pack_hilo(v0);
      pk[t*16+u*4+1] = pack_hilo(v1);
      pk[t*16+u*4+2] = pack_hilo(v2);
      pk[t*16+u*4+3] = pack_hilo(v3);
    }
  }
}

// single-pass packed epilogue store: full 128x128 transpose into dead W buffer
// (128*LDE = 16896 words <= W_WORDS), 2 syncs total.
__device__ __forceinline__ void epi_store_1p(const uint32_t pk[32], uint32_t* __restrict__ ebuf,
    __nv_bfloat16* __restrict__ ghi, __nv_bfloat16* __restrict__ glo,
    int row0, int tid, int wm, int wn, int gid, int tig){
  #pragma unroll
  for (int t=0;t<2;t++){
    int rA = wm*32 + t*16 + gid;
    int rB = rA + 8;
    #pragma unroll
    for (int u=0;u<4;u++){
      int cl = wn*32 + u*8 + 2*tig;
      ebuf[ cl   *LDE + rA] = pk[t*16+u*4+0];
      ebuf[(cl+1)*LDE + rA] = pk[t*16+u*4+1];
      ebuf[ cl   *LDE + rB] = pk[t*16+u*4+2];
      ebuf[(cl+1)*LDE + rB] = pk[t*16+u*4+3];
    }
  }
  __syncthreads();
  {
    int rb = tid & 15;
    int cb = tid >> 4;            // 0..31
    #pragma unroll
    for (int p=0;p<4;p++){
      int cl = cb + 32*p;
      #pragma unroll
      for (int h=0; h<2; h++){
        int rq = rb + 16*h;
        uint4 w = *reinterpret_cast<const uint4*>(&ebuf[cl*LDE + rq*4]);
        uint32_t hi01 = prmt_(w.x, w.y, 0x5410u);
        uint32_t hi23 = prmt_(w.z, w.w, 0x5410u);
        uint32_t lo01 = prmt_(w.x, w.y, 0x7632u);
        uint32_t lo23 = prmt_(w.z, w.w, 0x7632u);
        size_t base = (size_t)cl*NROWS + row0 + rq*4;
        *reinterpret_cast<uint2*>(&ghi[base]) = make_uint2(hi01, hi23);
        *reinterpret_cast<uint2*>(&glo[base]) = make_uint2(lo01, lo23);
      }
    }
  }
  __syncthreads();
}

__global__ __launch_bounds__(512) void proj_all_kernel(
    const float* __restrict__ act, const float* __restrict__ lng, const float* __restrict__ lnb,
    const float* __restrict__ mask,
    const float* __restrict__ Wl,  const float* __restrict__ bl,
    const float* __restrict__ Wgl, const float* __restrict__ bgl,
    const float* __restrict__ Wr,  const float* __restrict__ br,
    const float* __restrict__ Wgr, const float* __restrict__ bgr,
    const float* __restrict__ Wg,  const float* __restrict__ bg,
    __nv_bfloat16* __restrict__ gLh, __nv_bfloat16* __restrict__ gLl,
    __nv_bfloat16* __restrict__ gRh, __nv_bfloat16* __restrict__ gRl,
    float* __restrict__ gate){
  extern __shared__ uint32_t sm[];
  uint32_t* xs   = sm;
  uint32_t* w1   = sm + XS_WORDS;
  uint32_t* w2   = w1 + W_WORDS;
  int tid  = threadIdx.x;
  int row0 = blockIdx.x * 128;
  int kv   = tid & 31;

  // ---- fused staging: act LDG + in-register LN + tf32 STS; W1/W2 via reg roundtrip ----
  {
    uint4 va[8];
    #pragma unroll
    for (int it=0; it<8; ++it){
      int r = (tid>>5) + it*16;
      va[it] = *reinterpret_cast<const uint4*>(&act[(size_t)(row0+r)*CDIM + kv*4]);
    }
    uint4 wA[8], wB[8];
    ldgW(Wl,  tid, wA);
    ldgW(Wgl, tid, wB);
    float4 g4 = *reinterpret_cast<const float4*>(&lng[kv*4]);
    float4 b4 = *reinterpret_cast<const float4*>(&lnb[kv*4]);
    #pragma unroll
    for (int it=0; it<8; ++it){
      int r = (tid>>5) + it*16;
      float4 v = *reinterpret_cast<const float4*>(&va[it]);
      float s  = v.x + v.y + v.z + v.w;
      float s2 = v.x*v.x + v.y*v.y + v.z*v.z + v.w*v.w;
      #pragma unroll
      for (int off=16; off>0; off>>=1){
        s  += __shfl_xor_sync(0xffffffffu, s,  off);
        s2 += __shfl_xor_sync(0xffffffffu, s2, off);
      }
      float mu = s * (1.f/128.f);
      float rs = rsqrtf(s2*(1.f/128.f) - mu*mu + EPSV);
      uint4 t;
      t.x = tf32_rna((v.x-mu)*rs*g4.x + b4.x);
      t.y = tf32_rna((v.y-mu)*rs*g4.y + b4.y);
      t.z = tf32_rna((v.z-mu)*rs*g4.z + b4.z);
      t.w = tf32_rna((v.w-mu)*rs*g4.w + b4.w);
      *reinterpret_cast<uint4*>(&xs[r*LDX + kv*4]) = t;
    }
    stsW(wA, tid, w1);
    stsW(wB, tid, w2);
  }
  __syncthreads();

  int lane = tid&31, wid = tid>>5;
  int wm = wid>>2, wn = wid&3;
  int gid = lane>>2, tig = lane&3;

  float acc1[2][4][4], acc2[2][4][4];
  uint32_t pk[32];

  // ---- GEMM 1: left (dual) ----
  #pragma unroll
  for (int t=0;t<2;t++)
    #pragma unroll
    for (int u=0;u<4;u++)
      #pragma unroll
      for (int r=0;r<4;r++){ acc1[t][u][r]=0.f; acc2[t][u][r]=0.f; }
  gemm_pair(xs, w1, w2, wm, wn, gid, tig, acc1, acc2, true);
  compute_pk(acc1, acc2, mask, bl, bgl, row0, wm, wn, gid, tig, pk);
  __syncthreads();                 // all warps done reading w1/w2
  {
    uint4 wA[8], wB[8];
    ldgW(Wr,  tid, wA);            // prefetch next W pair under epilogue
    ldgW(Wgr, tid, wB);
    epi_store_1p(pk, w1, gLh, gLl, row0, tid, wm, wn, gid, tig);
    stsW(wA, tid, w1);
    stsW(wB, tid, w2);
  }
  __syncthreads();

  // ---- GEMM 2: right (dual) ----
  #pragma unroll
  for (int t=0;t<2;t++)
    #pragma unroll
    for (int u=0;u<4;u++)
      #pragma unroll
      for (int r=0;r<4;r++){ acc1[t][u][r]=0.f; acc2[t][u][r]=0.f; }
  gemm_pair(xs, w1, w2, wm, wn, gid, tig, acc1, acc2, true);
  compute_pk(acc1, acc2, mask, br, bgr, row0, wm, wn, gid, tig, pk);
  __syncthreads();
  {
    uint4 wA[8];
    ldgW(Wg, tid, wA);             // prefetch gate W under epilogue
    epi_store_1p(pk, w1, gRh, gRl, row0, tid, wm, wn, gid, tig);
    stsW(wA, tid, w1);
  }
  __syncthreads();

  // ---- GEMM 3: gate (single) ----
  #pragma unroll
  for (int t=0;t<2;t++)
    #pragma unroll
    for (int u=0;u<4;u++)
      #pragma unroll
      for (int r=0;r<4;r++) acc1[t][u][r]=0.f;
  gemm_pair(xs, w1, w1, wm, wn, gid, tig, acc1, acc2, false);
  #pragma unroll
  for (int t=0;t<2;t++){
    int rowA = row0 + wm*32 + t*16 + gid;
    int rowB = rowA + 8;
    #pragma unroll
    for (int u=0;u<4;u++){
      int colb = wn*32 + u*8 + 2*tig;
      float b0 = bg[colb], b1 = bg[colb+1];
      float2 oA, oB;
      oA.x = fsig(acc1[t][u][0]+b0);
      oA.y = fsig(acc1[t][u][1]+b1);
      oB.x = fsig(acc1[t][u][2]+b0);
      oB.y = fsig(acc1[t][u][3]+b1);
      *reinterpret_cast<float2*>(&gate[(size_t)rowA*CDIM + colb]) = oA;
      *reinterpret_cast<float2*>(&gate[(size_t)rowB*CDIM + colb]) = oB;
    }
  }
}

// ============== Stage 3: per-channel GEMM via bf16-split mma ==============
#define TRI_LDS 72
#define TRI_SMEM ((64*TRI_LDS*2 + 128*TRI_LDS*2)*2)
__global__ __launch_bounds__(256, 2) void tri_kernel(){
  extern __shared__ __nv_bfloat16 smb[];
  __nv_bfloat16* Lhi = smb;
  __nv_bfloat16* Llo = smb + 64*TRI_LDS;
  __nv_bfloat16* Rhi = smb + 2*64*TRI_LDS;
  __nv_bfloat16* Rlo = Rhi + 128*TRI_LDS;
  uint32_t sLhi = smem_u32(Lhi);
  uint32_t sLlo = smem_u32(Llo);
  uint32_t sRhi = smem_u32(Rhi);
  uint32_t sRlo = smem_u32(Rlo);
  int tid = threadIdx.x;
  int c  = blockIdx.z;
  int i0 = blockIdx.x * 64;
  int j0 = blockIdx.y * 128;
  const __nv_bfloat16* gLh = g_Lhi + (size_t)c*NROWS;
  const __nv_bfloat16* gLl = g_Llo + (size_t)c*NROWS;
  const __nv_bfloat16* gRh = g_Rhi + (size_t)c*NROWS;
  const __nv_bfloat16* gRl = g_Rlo + (size_t)c*NROWS;

  int lane = tid&31, wid = tid>>5;
  int wm = wid>>2, wn = wid&3;
  int gid = lane>>2, tig = lane&3;

  int sr = tid>>3, sseg = tid&7;

  float acc[2][4][4];
  #pragma unroll
  for (int t=0;t<2;t++)
    #pragma unroll
    for (int u=0;u<4;u++)
      #pragma unroll
      for (int r=0;r<4;r++) acc[t][u][r]=0.f;

  for (int kc=0; kc<NTOK; kc+=64){
    __syncthreads();
    #pragma unroll
    for (int it=0; it<2; it++){
      int r = sr + it*32;
      size_t go = (size_t)(i0+r)*NTOK + kc + sseg*8;
      uint32_t so = (uint32_t)(r*TRI_LDS + sseg*8)*2;
      cp16(sLhi + so, &gLh[go]);
      cp16(sLlo + so, &gLl[go]);
    }
    #pragma unroll
    for (int it=0; it<4; it++){
      int r = sr + it*32;
      size_t go = (size_t)(j0+r)*NTOK + kc + sseg*8;
      uint32_t so = (uint32_t)(r*TRI_LDS + sseg*8)*2;
      cp16(sRhi + so, &gRh[go]);
      cp16(sRlo + so, &gRl[go]);
    }
    cp_commit_wait();
    __syncthreads();

    #pragma unroll
    for (int ks=0; ks<4; ks++){
      int ko = ks*16;
      uint32_t ah[2][4], al[2][4];
      #pragma unroll
      for (int t=0;t<2;t++){
        int row = wm*32 + t*16 + gid;
        int base = row*TRI_LDS + ko + 2*tig;
        ah[t][0] = *reinterpret_cast<const uint32_t*>(&Lhi[base]);
        ah[t][1] = *reinterpret_cast<const uint32_t*>(&Lhi[base + 8*TRI_LDS]);
        ah[t][2] = *reinterpret_cast<const uint32_t*>(&Lhi[base + 8]);
        ah[t][3] = *reinterpret_cast<const uint32_t*>(&Lhi[base + 8*TRI_LDS + 8]);
        al[t][0] = *reinterpret_cast<const uint32_t*>(&Llo[base]);
        al[t][1] = *reinterpret_cast<const uint32_t*>(&Llo[base + 8*TRI_LDS]);
        al[t][2] = *reinterpret_cast<const uint32_t*>(&Llo[base + 8]);
        al[t][3] = *reinterpret_cast<const uint32_t*>(&Llo[base + 8*TRI_LDS + 8]);
      }
      #pragma unroll
      for (int u=0;u<4;u++){
        int jrow = wn*32 + u*8 + gid;
        int bb = jrow*TRI_LDS + ko + 2*tig;
        uint32_t bh0 = *reinterpret_cast<const uint32_t*>(&Rhi[bb]);
        uint32_t bh1 = *reinterpret_cast<const uint32_t*>(&Rhi[bb + 8]);
        uint32_t bl0 = *reinterpret_cast<const uint32_t*>(&Rlo[bb]);
        uint32_t bl1 = *reinterpret_cast<const uint32_t*>(&Rlo[bb + 8]);
        #pragma unroll
        for (int t=0;t<2;t++){
          mma_bf16(acc[t][u], ah[t], bh0, bh1);
          mma_bf16(acc[t][u], ah[t], bl0, bl1);
          mma_bf16(acc[t][u], al[t], bh0, bh1);
        }
      }
    }
  }

  float* To = g_tri + (size_t)c*NROWS;
  #pragma unroll
  for (int t=0;t<2;t++){
    int iA = i0 + wm*32 + t*16 + gid;
    int iB = iA + 8;
    #pragma unroll
    for (int u=0;u<4;u++){
      int j = j0 + wn*32 + u*8 + 2*tig;
      float2 vA = {acc[t][u][0], acc[t][u][1]};
      float2 vB = {acc[t][u][2], acc[t][u][3]};
      *reinterpret_cast<float2*>(&To[(size_t)iA*NTOK + j]) = vA;
      *reinterpret_cast<float2*>(&To[(size_t)iB*NTOK + j]) = vB;
    }
  }
}

// ============== Stage 4: LN(tri) @ Wo + bo, * gate (tf32 mma) ==============
#define LDT 129
#define FINAL_SMEM ((128*LDT + XS_WORDS + W_WORDS)*4)
__global__ __launch_bounds__(512) void final_kernel(const float* __restrict__ cg,
                                                    const float* __restrict__ cb,
                                                    const float* __restrict__ Wo,
                                                    const float* __restrict__ bo,
                                                    float* __restrict__ out){
  extern __shared__ uint32_t sm[];
  float*    T  = reinterpret_cast<float*>(sm);
  uint32_t* xs = sm + 128*LDT;
  uint32_t* w  = xs + XS_WORDS;
  __shared__ float p1[4][128], p2[4][128], mu_s[128], rs_s[128];
  int tid  = threadIdx.x;
  int row0 = blockIdx.x * 128;

  #pragma unroll
  for (int it=0; it<8; ++it){
    int slot = tid + it*512;
    int cch = slot >> 5;
    int v4  = slot & 31;
    float4 v = *reinterpret_cast<const float4*>(&g_tri[(size_t)cch*NROWS + row0 + v4*4]);
    T[cch*LDT + v4*4 + 0] = v.x;
    T[cch*LDT + v4*4 + 1] = v.y;
    T[cch*LDT + v4*4 + 2] = v.z;
    T[cch*LDT + v4*4 + 3] = v.w;
    v = *reinterpret_cast<const float4*>(&Wo[cch*CDIM + v4*4]);
    uint4 t; t.x=tf32_rna(v.x); t.y=tf32_rna(v.y); t.z=tf32_rna(v.z); t.w=tf32_rna(v.w);
    *reinterpret_cast<uint4*>(&w[cch*LDW + v4*4]) = t;
  }
  __syncthreads();

  {
    int ij = tid & 127, pp = tid >> 7;
    float s=0.f, s2=0.f;
    #pragma unroll
    for (int k=0;k<32;k++){
      float v = T[(pp*32+k)*LDT + ij];
      s += v; s2 += v*v;
    }
    p1[pp][ij] = s; p2[pp][ij] = s2;
  }
  __syncthreads();
  if (tid < 128){
    float s  = p1[0][tid]+p1[1][tid]+p1[2][tid]+p1[3][tid];
    float s2 = p2[0][tid]+p2[1][tid]+p2[2][tid]+p2[3][tid];
    float mu = s*(1.f/128.f);
    mu_s[tid] = mu;
    rs_s[tid] = rsqrtf(s2*(1.f/128.f) - mu*mu + EPSV);
  }
  __syncthreads();

  #pragma unroll
  for (int it=0; it<8; ++it){
    int slot = tid + it*512;
    int r  = slot & 127;
    int cq = slot >> 7;
    float mu = mu_s[r], rs = rs_s[r];
    uint4 t;
    {
      int c0 = cq*4;
      float v0 = (T[(c0+0)*LDT + r]-mu)*rs*cg[c0+0] + cb[c0+0];
      float v1 = (T[(c0+1)*LDT + r]-mu)*rs*cg[c0+1] + cb[c0+1];
      float v2 = (T[(c0+2)*LDT + r]-mu)*rs*cg[c0+2] + cb[c0+2];
      float v3 = (T[(c0+3)*LDT + r]-mu)*rs*cg[c0+3] + cb[c0+3];
      t.x=tf32_rna(v0); t.y=tf32_rna(v1); t.z=tf32_rna(v2); t.w=tf32_rna(v3);
    }
    *reinterpret_cast<uint4*>(&xs[r*LDX + cq*4]) = t;
  }
  __syncthreads();

  int lane = tid&31, wid = tid>>5;
  int wm = wid>>2, wn = wid&3;
  int gid = lane>>2, tig = lane&3;

  float acc[2][4][4], accd[2][4][4];
  #pragma unroll
  for (int t=0;t<2;t++)
    #pragma unroll
    for (int u=0;u<4;u++)
      #pragma unroll
      for (int r=0;r<4;r++) acc[t][u][r]=0.f;

  gemm_pair(xs, w, w, wm, wn, gid, tig, acc, accd, false);

  #pragma unroll
  for (int t=0;t<2;t++){
    int rowA = row0 + wm*32 + t*16 + gid;
    int rowB = rowA + 8;
    #pragma unroll
    for (int u=0;u<4;u++){
      int colb = wn*32 + u*8 + 2*tig;
      float bo0 = bo[colb], bo1 = bo[colb+1];
      float2 gA = *reinterpret_cast<const float2*>(&g_gate[(size_t)rowA*CDIM + colb]);
      float2 gB = *reinterpret_cast<const float2*>(&g_gate[(size_t)rowB*CDIM + colb]);
      float2 oA, oB;
      oA.x = (acc[t][u][0]+bo0)*gA.x;
      oA.y = (acc[t][u][1]+bo1)*gA.y;
      oB.x = (acc[t][u][2]+bo0)*gB.x;
      oB.y = (acc[t][u][3]+bo1)*gB.y;
      *reinterpret_cast<float2*>(&out[(size_t)rowA*CDIM + colb]) = oA;
      *reinterpret_cast<float2*>(&out[(size_t)rowB*CDIM + colb]) = oB;
    }
  }
}

extern "C" void kernel_launch(void* const* d_in, const int* in_sizes, int n_in,
                              void* d_out, int out_size) {
  const float* act  = (const float*)d_in[0];
  const float* mask = (const float*)d_in[1];
  const float* ln_g = (const float*)d_in[2];
  const float* ln_b = (const float*)d_in[3];
  const float* Wl   = (const float*)d_in[4];
  const float* bl   = (const float*)d_in[5];
  const float* Wr   = (const float*)d_in[6];
  const float* br   = (const float*)d_in[7];
  const float* Wgl  = (const float*)d_in[8];
  const float* bgl  = (const float*)d_in[9];
  const float* Wgr  = (const float*)d_in[10];
  const float* bgr  = (const float*)d_in[11];
  const float* cg   = (const float*)d_in[12];
  const float* cb   = (const float*)d_in[13];
  const float* Wo   = (const float*)d_in[14];
  const float* bo   = (const float*)d_in[15];
  const float* Wg   = (const float*)d_in[16];
  const float* bg   = (const float*)d_in[17];
  float* out = (float*)d_out;

  __nv_bfloat16 *dLh=nullptr, *dLl=nullptr, *dRh=nullptr, *dRl=nullptr;
  float *dGate=nullptr;
  cudaGetSymbolAddress((void**)&dLh, g_Lhi);
  cudaGetSymbolAddress((void**)&dLl, g_Llo);
  cudaGetSymbolAddress((void**)&dRh, g_Rhi);
  cudaGetSymbolAddress((void**)&dRl, g_Rlo);
  cudaGetSymbolAddress((void**)&dGate, g_gate);

  cudaFuncSetAttribute(proj_all_kernel, cudaFuncAttributeMaxDynamicSharedMemorySize, PROJALL_SMEM);
  cudaFuncSetAttribute(tri_kernel,      cudaFuncAttributeMaxDynamicSharedMemorySize, TRI_SMEM);
  cudaFuncSetAttribute(final_kernel,    cudaFuncAttributeMaxDynamicSharedMemorySize, FINAL_SMEM);

  proj_all_kernel<<<NROWS/128, 512, PROJALL_SMEM>>>(act, ln_g, ln_b, mask,
      Wl, bl, Wgl, bgl, Wr, br, Wgr, bgr, Wg, bg,
      dLh, dLl, dRh, dRl, dGate);
  tri_kernel<<<dim3(NTOK/64, NTOK/128, CDIM), 256, TRI_SMEM>>>();
  final_kernel<<<NROWS/128, 512, FINAL_SMEM>>>(cg, cb, Wo, bo, out);
}